// round 2
// baseline (speedup 1.0000x reference)
#include <cuda_runtime.h>
#include <cuda_bf16.h>

#define BB   128
#define TT   256
#define DD   512
#define HH   1024
#define G4   4096
#define CC   1000
#define NCTA 128
#define NTHR 256

// ---------------- device scratch ----------------
__device__ float g_zx[(size_t)BB * TT * G4];          // [(b*T+t)][4096]
__device__ int4  g_xhi4[BB * TT * DD / 8];
__device__ int4  g_xlo4[BB * TT * DD / 8];
__device__ int4  g_wxhi4[DD * G4 / 8];
__device__ int4  g_wxlo4[DD * G4 / 8];
__device__ int4  g_wpk4[(size_t)NCTA * 64 * HH / 8];  // [cta][j:64][k:1024] bf16
__device__ int4  g_hbhi4[2][BB * HH / 8];
__device__ int4  g_hblo4[2][BB * HH / 8];
__device__ float g_hT[BB * HH];
__device__ unsigned g_gen;
__device__ unsigned g_cnt;

__device__ __forceinline__ float sigmoidf_(float x) { return 1.0f / (1.0f + __expf(-x)); }

__device__ __forceinline__ void split_us(float v, unsigned short &h, unsigned short &l) {
    __nv_bfloat16 bh = __float2bfloat16_rn(v);
    float r = v - __bfloat162float(bh);
    h = __bfloat16_as_ushort(bh);
    l = __bfloat16_as_ushort(__float2bfloat16_rn(r));
}

__device__ __forceinline__ void mma_acc(float (&c)[4], const unsigned (&a)[4],
                                        unsigned b0, unsigned b1) {
    asm volatile(
        "mma.sync.aligned.m16n8k16.row.col.f32.bf16.bf16.f32 "
        "{%0,%1,%2,%3}, {%4,%5,%6,%7}, {%8,%9}, {%0,%1,%2,%3};\n"
        : "+f"(c[0]), "+f"(c[1]), "+f"(c[2]), "+f"(c[3])
        : "r"(a[0]), "r"(a[1]), "r"(a[2]), "r"(a[3]), "r"(b0), "r"(b1));
}

__device__ __forceinline__ void grid_bar(unsigned &gen) {
    __threadfence();
    __syncthreads();
    if (threadIdx.x == 0) {
        if (atomicAdd(&g_cnt, 1u) == NCTA - 1u) {
            g_cnt = 0u;
            __threadfence();
            atomicExch(&g_gen, gen + 1u);
        } else {
            while (atomicAdd(&g_gen, 0u) == gen) __nanosleep(32);
        }
    }
    __syncthreads();
    gen++;
}

__global__ void __launch_bounds__(NTHR, 1)
lstm_persistent(const float* __restrict__ x, const float* __restrict__ Wk,
                const float* __restrict__ bk, const float* __restrict__ w,
                const float* __restrict__ bo, float* __restrict__ out) {
    __shared__ __align__(16) unsigned char s_raw[46080];

    const int tid  = threadIdx.x;
    const int blk  = blockIdx.x;
    const int wid  = tid >> 5;
    const int lane = tid & 31;
    const int gq   = lane >> 2;
    const int tig  = lane & 3;

    unsigned gen = atomicAdd(&g_gen, 0u);

    const int gtid = blk * NTHR + tid;
    const int gstr = NCTA * NTHR;

    // ===== Phase A: precision splits + Wh repack =====
    {
        const float4* x4 = (const float4*)x;
        ushort4* xh = (ushort4*)g_xhi4;
        ushort4* xl = (ushort4*)g_xlo4;
        for (int i = gtid; i < BB * TT * DD / 4; i += gstr) {
            float4 v = x4[i];
            ushort4 h, l;
            split_us(v.x, h.x, l.x); split_us(v.y, h.y, l.y);
            split_us(v.z, h.z, l.z); split_us(v.w, h.w, l.w);
            xh[i] = h; xl[i] = l;
        }
        const float4* wk4 = (const float4*)Wk;   // rows 0..511 = Wx
        ushort4* wh = (ushort4*)g_wxhi4;
        ushort4* wl = (ushort4*)g_wxlo4;
        for (int i = gtid; i < DD * G4 / 4; i += gstr) {
            float4 v = wk4[i];
            ushort4 h, l;
            split_us(v.x, h.x, l.x); split_us(v.y, h.y, l.y);
            split_us(v.z, h.z, l.z); split_us(v.w, h.w, l.w);
            wh[i] = h; wl[i] = l;
        }
        unsigned short* wpk = (unsigned short*)g_wpk4;
        for (int i = gtid; i < NCTA * 64 * HH; i += gstr) {
            int k  = i & (HH - 1);
            int j  = (i >> 10) & 63;
            int bq = i >> 16;
            int lc = j & 31, part = j >> 5;
            int col = ((lc >> 3) << 10) + (bq << 3) + (lc & 7);
            float v = Wk[(size_t)(DD + k) * G4 + col];
            __nv_bfloat16 bh = __float2bfloat16_rn(v);
            unsigned short us = part
                ? __bfloat16_as_ushort(__float2bfloat16_rn(v - __bfloat162float(bh)))
                : __bfloat16_as_ushort(bh);
            wpk[i] = us;
        }
        int4 z4 = make_int4(0, 0, 0, 0);
        for (int i = gtid; i < BB * HH / 8; i += gstr) {
            g_hbhi4[0][i] = z4; g_hbhi4[1][i] = z4;
            g_hblo4[0][i] = z4; g_hblo4[1][i] = z4;
        }
    }
    grid_bar(gen);

    // ===== Phase B: Zx = x @ Wx + bk =====
    {
        int4* sAhi4 = (int4*)(s_raw);
        int4* sAlo4 = (int4*)(s_raw + 9216);
        unsigned short* sBthi = (unsigned short*)(s_raw + 18432);
        unsigned short* sBtlo = (unsigned short*)(s_raw + 27648);
        const unsigned* uAhi = (const unsigned*)(s_raw);
        const unsigned* uAlo = (const unsigned*)(s_raw + 9216);
        const unsigned* uBhi = (const unsigned*)(s_raw + 18432);
        const unsigned* uBlo = (const unsigned*)(s_raw + 27648);
        const unsigned* wxh = (const unsigned*)g_wxhi4;
        const unsigned* wxl = (const unsigned*)g_wxlo4;
        const int wm = wid >> 1, wn = wid & 1;

        for (int tile = blk; tile < 512 * 64; tile += NCTA) {
            const int tn = tile & 63, tm = tile >> 6;
            const int m0 = tm * 64, n0 = tn * 64;
            float acc[4][4] = {};
            for (int kc0 = 0; kc0 < DD; kc0 += 64) {
                __syncthreads();
#pragma unroll
                for (int j2 = 0; j2 < 2; j2++) {
                    int e = tid + j2 * 256;
                    int row = e >> 3, q = e & 7;
                    int src = (m0 + row) * 64 + (kc0 >> 3) + q;
                    sAhi4[row * 9 + q] = g_xhi4[src];
                    sAlo4[row * 9 + q] = g_xlo4[src];
                }
#pragma unroll
                for (int j2 = 0; j2 < 8; j2++) {
                    int e = tid + j2 * 256;
                    int k = e >> 5, np = e & 31;
                    int srcu = (kc0 + k) * 2048 + (n0 >> 1) + np;
                    unsigned vh = wxh[srcu], vl = wxl[srcu];
                    int nn = 2 * np;
                    sBthi[nn * 72 + k]       = (unsigned short)(vh & 0xffffu);
                    sBthi[(nn + 1) * 72 + k] = (unsigned short)(vh >> 16);
                    sBtlo[nn * 72 + k]       = (unsigned short)(vl & 0xffffu);
                    sBtlo[(nn + 1) * 72 + k] = (unsigned short)(vl >> 16);
                }
                __syncthreads();
#pragma unroll
                for (int ks = 0; ks < 4; ks++) {
                    unsigned ahi[4], alo[4];
                    const int kh = ks * 8 + tig;
#pragma unroll
                    for (int jj = 0; jj < 4; jj++) {
                        int row = wm * 16 + gq + (jj & 1) * 8;
                        int idx = row * 36 + kh + (jj >> 1) * 4;
                        ahi[jj] = uAhi[idx]; alo[jj] = uAlo[idx];
                    }
#pragma unroll
                    for (int nt = 0; nt < 4; nt++) {
                        int nb = wn * 32 + nt * 8 + gq;
                        int bidx = nb * 36 + kh;
                        unsigned bh0 = uBhi[bidx], bh1 = uBhi[bidx + 4];
                        unsigned bl0 = uBlo[bidx], bl1 = uBlo[bidx + 4];
                        mma_acc(acc[nt], ahi, bh0, bh1);
                        mma_acc(acc[nt], ahi, bl0, bl1);
                        mma_acc(acc[nt], alo, bh0, bh1);
                    }
                }
            }
#pragma unroll
            for (int nt = 0; nt < 4; nt++)
#pragma unroll
                for (int f = 0; f < 4; f++) {
                    int row = m0 + wm * 16 + gq + (f >> 1) * 8;
                    int cn  = n0 + wn * 32 + nt * 8 + 2 * tig + (f & 1);
                    g_zx[(size_t)row * G4 + cn] = acc[nt][f] + __ldg(&bk[cn]);
                }
        }
    }
    grid_bar(gen);

    // ===== Phase C: 256 recurrent steps =====
    {
        int4* sH4hi = (int4*)(s_raw);
        int4* sH4lo = (int4*)(s_raw + 18432);
        int4* sW4hi = (int4*)(s_raw + 36864);
        int4* sW4lo = (int4*)(s_raw + 41472);
        const unsigned* uHhi = (const unsigned*)(s_raw);
        const unsigned* uHlo = (const unsigned*)(s_raw + 18432);
        const unsigned* uWhi = (const unsigned*)(s_raw + 36864);
        const unsigned* uWlo = (const unsigned*)(s_raw + 41472);
        __nv_bfloat16* hbh0 = (__nv_bfloat16*)g_hbhi4[0];
        __nv_bfloat16* hbh1 = (__nv_bfloat16*)g_hbhi4[1];
        __nv_bfloat16* hbl0 = (__nv_bfloat16*)g_hblo4[0];
        __nv_bfloat16* hbl1 = (__nv_bfloat16*)g_hblo4[1];

        float cst[4] = {0.f, 0.f, 0.f, 0.f};

        for (int t = 0; t < TT; t++) {
            const int p = t & 1;
            float acc[4][4] = {};
            for (int kc0 = 0; kc0 < HH; kc0 += 64) {
                __syncthreads();
#pragma unroll
                for (int j2 = 0; j2 < 4; j2++) {
                    int e = tid + j2 * 256;
                    int row = e >> 3, q = e & 7;
                    int src = row * 128 + (kc0 >> 3) + q;
                    sH4hi[row * 9 + q] = g_hbhi4[p][src];
                    sH4lo[row * 9 + q] = g_hblo4[p][src];
                }
#pragma unroll
                for (int j2 = 0; j2 < 2; j2++) {
                    int e = tid + j2 * 256;
                    int j = e >> 3, q = e & 7;
                    int lc = j & 31;
                    int4 v = g_wpk4[(blk * 64 + j) * 128 + (kc0 >> 3) + q];
                    if (j2 == 0) sW4hi[lc * 9 + q] = v;
                    else         sW4lo[lc * 9 + q] = v;
                }
                __syncthreads();
#pragma unroll
                for (int ks = 0; ks < 4; ks++) {
                    unsigned ahi[4], alo[4];
                    const int kh = ks * 8 + tig;
#pragma unroll
                    for (int jj = 0; jj < 4; jj++) {
                        int row = wid * 16 + gq + (jj & 1) * 8;
                        int idx = row * 36 + kh + (jj >> 1) * 4;
                        ahi[jj] = uHhi[idx]; alo[jj] = uHlo[idx];
                    }
#pragma unroll
                    for (int nt = 0; nt < 4; nt++) {
                        int nb = nt * 8 + gq;
                        int bidx = nb * 36 + kh;
                        unsigned bh0 = uWhi[bidx], bh1 = uWhi[bidx + 4];
                        unsigned bl0 = uWlo[bidx], bl1 = uWlo[bidx + 4];
                        mma_acc(acc[nt], ahi, bh0, bh1);
                        mma_acc(acc[nt], ahi, bl0, bl1);
                        mma_acc(acc[nt], alo, bh0, bh1);
                    }
                }
            }
#pragma unroll
            for (int f = 0; f < 4; f++) {
                int b_ = wid * 16 + gq + (f >> 1) * 8;
                int hu_off = 2 * tig + (f & 1);
                size_t zb = ((size_t)b_ * TT + t) * G4 + (blk << 3) + hu_off;
                float zi = acc[0][f] + g_zx[zb];
                float zj = acc[1][f] + g_zx[zb + 1024];
                float zf = acc[2][f] + g_zx[zb + 2048];
                float zo = acc[3][f] + g_zx[zb + 3072];
                float cn = cst[f] * sigmoidf_(zf + 1.0f) + sigmoidf_(zi) * tanhf(zj);
                float hn = sigmoidf_(zo) * tanhf(cn);
                cst[f] = cn;
                int hidx = b_ * HH + (blk << 3) + hu_off;
                __nv_bfloat16 bh = __float2bfloat16_rn(hn);
                __nv_bfloat16 bl = __float2bfloat16_rn(hn - __bfloat162float(bh));
                if (p) { hbh0[hidx] = bh; hbl0[hidx] = bl; }
                else   { hbh1[hidx] = bh; hbl1[hidx] = bl; }
                if (t == TT - 1) g_hT[hidx] = hn;
            }
            grid_bar(gen);
        }
    }

    // ===== Phase D: out = hT @ w + bo =====
    {
        float* sh = (float*)s_raw;
        const int b_ = blk;
        for (int k = tid; k < HH; k += NTHR) sh[k] = g_hT[b_ * HH + k];
        __syncthreads();
        for (int c = tid; c < CC; c += NTHR) {
            float acc = bo[c];
#pragma unroll 8
            for (int k = 0; k < HH; k++) acc = fmaf(sh[k], w[k * CC + c], acc);
            out[b_ * CC + c] = acc;
        }
    }
}

extern "C" void kernel_launch(void* const* d_in, const int* in_sizes, int n_in,
                              void* d_out, int out_size) {
    (void)in_sizes; (void)n_in; (void)out_size;
    const float* x  = (const float*)d_in[0];
    const float* Wk = (const float*)d_in[1];
    const float* bk = (const float*)d_in[2];
    const float* w  = (const float*)d_in[3];
    const float* b  = (const float*)d_in[4];
    float* out = (float*)d_out;
    lstm_persistent<<<NCTA, NTHR>>>(x, Wk, bk, w, b, out);
}

// round 3
// speedup vs baseline: 1.4971x; 1.4971x over previous
#include <cuda_runtime.h>
#include <cuda_bf16.h>

#define BB   128
#define TT   256
#define DD   512
#define HH   1024
#define G4   4096
#define CC   1000
#define NCTA 128
#define NTHR 256

// dynamic smem layout (bytes)
#define C_H0    132096      // phase C: W resident [64 rows][2064B], then H bufs
#define C_HBUF  36864       // one H buf: hi 18432 + lo 18432
#define B_ABASE 133120      // phase B: B resident 2x66560, then A bufs
#define B_ABUF  18432       // one A buf: hi 9216 + lo 9216
#define DYN_SMEM 205824

// ---------------- device scratch ----------------
__device__ float g_zx[(size_t)BB * TT * G4];
__device__ int4  g_xhi4[BB * TT * DD / 8];
__device__ int4  g_xlo4[BB * TT * DD / 8];
__device__ int4  g_wxhi4[DD * G4 / 8];                // TRANSPOSED [n:4096][k:512] bf16
__device__ int4  g_wxlo4[DD * G4 / 8];
__device__ int4  g_wpk4[(size_t)NCTA * 64 * HH / 8];  // [cta][j:64][k:1024] bf16
__device__ int4  g_hbhi4[2][BB * HH / 8];
__device__ int4  g_hblo4[2][BB * HH / 8];
__device__ float g_hT[BB * HH];
__device__ unsigned g_gen;
__device__ unsigned g_cnt;

__device__ __forceinline__ float sigmoidf_(float x) { return 1.0f / (1.0f + __expf(-x)); }

__device__ __forceinline__ void split_us(float v, unsigned short &h, unsigned short &l) {
    __nv_bfloat16 bh = __float2bfloat16_rn(v);
    float r = v - __bfloat162float(bh);
    h = __bfloat16_as_ushort(bh);
    l = __bfloat16_as_ushort(__float2bfloat16_rn(r));
}

__device__ __forceinline__ void mma_acc(float* c, const unsigned* a, unsigned b0, unsigned b1) {
    asm volatile(
        "mma.sync.aligned.m16n8k16.row.col.f32.bf16.bf16.f32 "
        "{%0,%1,%2,%3}, {%4,%5,%6,%7}, {%8,%9}, {%0,%1,%2,%3};\n"
        : "+f"(c[0]), "+f"(c[1]), "+f"(c[2]), "+f"(c[3])
        : "r"(a[0]), "r"(a[1]), "r"(a[2]), "r"(a[3]), "r"(b0), "r"(b1));
}

__device__ __forceinline__ void ldsm4(unsigned* r, unsigned a) {
    asm volatile("ldmatrix.sync.aligned.m8n8.x4.shared.b16 {%0,%1,%2,%3}, [%4];\n"
                 : "=r"(r[0]), "=r"(r[1]), "=r"(r[2]), "=r"(r[3]) : "r"(a));
}

__device__ __forceinline__ void cpa16(unsigned s, const void* g) {
    asm volatile("cp.async.cg.shared.global [%0], [%1], 16;\n" :: "r"(s), "l"(g) : "memory");
}
__device__ __forceinline__ void cpa_commit() { asm volatile("cp.async.commit_group;\n" ::: "memory"); }
__device__ __forceinline__ void cpa_wait0()  { asm volatile("cp.async.wait_group 0;\n" ::: "memory"); }

__device__ __forceinline__ void grid_bar(unsigned &gen) {
    __threadfence();
    __syncthreads();
    if (threadIdx.x == 0) {
        if (atomicAdd(&g_cnt, 1u) == NCTA - 1u) {
            g_cnt = 0u;
            __threadfence();
            atomicExch(&g_gen, gen + 1u);
        } else {
            volatile unsigned* vg = &g_gen;
            while (*vg == gen) __nanosleep(64);
        }
        __threadfence();
    }
    __syncthreads();
    gen++;
}

__device__ __forceinline__ void prefetch_h(unsigned sb, int tid, int p, int kc, int buf) {
    unsigned dst = sb + C_H0 + (unsigned)(buf * C_HBUF);
    const int4* hi = g_hbhi4[p];
    const int4* lo = g_hblo4[p];
#pragma unroll
    for (int j2 = 0; j2 < 4; j2++) {
        int e = tid + j2 * 256;
        int row = e >> 3, q = e & 7;
        int gi = row * 128 + kc * 8 + q;
        cpa16(dst + (unsigned)(row * 144 + q * 16), hi + gi);
        cpa16(dst + 18432u + (unsigned)(row * 144 + q * 16), lo + gi);
    }
}

__device__ __forceinline__ void prefetch_a(unsigned sb, int tid, int m0, int kc, int buf) {
    unsigned dst = sb + B_ABASE + (unsigned)(buf * B_ABUF);
#pragma unroll
    for (int j2 = 0; j2 < 2; j2++) {
        int e = tid + j2 * 256;
        int row = e >> 3, q = e & 7;
        int gi = (m0 + row) * 64 + kc * 8 + q;
        cpa16(dst + (unsigned)(row * 144 + q * 16), g_xhi4 + gi);
        cpa16(dst + 9216u + (unsigned)(row * 144 + q * 16), g_xlo4 + gi);
    }
}

extern __shared__ __align__(16) unsigned char smem[];

__global__ void __launch_bounds__(NTHR, 1)
lstm_persistent(const float* __restrict__ x, const float* __restrict__ Wk,
                const float* __restrict__ bk, const float* __restrict__ w,
                const float* __restrict__ bo, float* __restrict__ out) {
    const int tid  = threadIdx.x;
    const int blk  = blockIdx.x;
    const int wid  = tid >> 5;
    const int lane = tid & 31;
    const int gq   = lane >> 2;
    const int tig  = lane & 3;
    const unsigned sb = (unsigned)__cvta_generic_to_shared(smem);

    unsigned gen = atomicAdd(&g_gen, 0u);

    const int gtid = blk * NTHR + tid;
    const int gstr = NCTA * NTHR;

    // ===== Phase A: precision splits + repacks =====
    {
        const float4* x4 = (const float4*)x;
        ushort4* xh = (ushort4*)g_xhi4;
        ushort4* xl = (ushort4*)g_xlo4;
        for (int i = gtid; i < BB * TT * DD / 4; i += gstr) {
            float4 v = x4[i];
            ushort4 h, l;
            split_us(v.x, h.x, l.x); split_us(v.y, h.y, l.y);
            split_us(v.z, h.z, l.z); split_us(v.w, h.w, l.w);
            xh[i] = h; xl[i] = l;
        }
        // Wx split TRANSPOSED: [n][k]
        unsigned short* wth = (unsigned short*)g_wxhi4;
        unsigned short* wtl = (unsigned short*)g_wxlo4;
        for (int i = gtid; i < G4 * DD; i += gstr) {
            int n = i >> 9, k = i & 511;
            float v = Wk[(size_t)k * G4 + n];
            unsigned short h, l;
            split_us(v, h, l);
            wth[i] = h; wtl[i] = l;
        }
        // Wh repack per CTA, gate-gathered
        unsigned short* wpk = (unsigned short*)g_wpk4;
        for (int i = gtid; i < NCTA * 64 * HH; i += gstr) {
            int k  = i & (HH - 1);
            int j  = (i >> 10) & 63;
            int bq = i >> 16;
            int lc = j & 31, part = j >> 5;
            int col = ((lc >> 3) << 10) + (bq << 3) + (lc & 7);
            float v = Wk[(size_t)(DD + k) * G4 + col];
            __nv_bfloat16 bh = __float2bfloat16_rn(v);
            unsigned short us = part
                ? __bfloat16_as_ushort(__float2bfloat16_rn(v - __bfloat162float(bh)))
                : __bfloat16_as_ushort(bh);
            wpk[i] = us;
        }
        int4 z4 = make_int4(0, 0, 0, 0);
        for (int i = gtid; i < BB * HH / 8; i += gstr) {
            g_hbhi4[0][i] = z4; g_hbhi4[1][i] = z4;
            g_hblo4[0][i] = z4; g_hblo4[1][i] = z4;
        }
    }
    grid_bar(gen);

    // ===== Phase B: Zx = x @ Wx + bk  (B slab resident, A streamed) =====
    {
        const int n0 = (blk & 63) * 64;
        int4* sB4 = (int4*)smem;
        for (int i = tid; i < 64 * 64; i += NTHR) {
            int r = i >> 6, q = i & 63;
            sB4[r * 65 + q]        = g_wxhi4[(n0 + r) * 64 + q];
            sB4[4160 + r * 65 + q] = g_wxlo4[(n0 + r) * 64 + q];
        }
        const int wm = wid >> 1, wn = wid & 1;
        const int l15 = lane & 15;
        const unsigned koffA = (unsigned)((lane >> 4) << 4);
        const unsigned bko   = (unsigned)(((lane >> 3) & 1) << 4);
        const int bn = (lane & 7) + ((lane >> 4) << 3);
        const int rowA = wm * 16 + l15;
        const unsigned wb0 = sb + (unsigned)((wn * 32 + bn) * 1040) + bko;
        const unsigned wb1 = wb0 + 16u * 1040u;
        const unsigned wl0 = wb0 + 66560u;
        const unsigned wl1 = wb1 + 66560u;

        prefetch_a(sb, tid, (blk >> 6) * 64, 0, 0);
        cpa_commit();
        for (int s = 0; s < 256; s++) {
            const int m0 = ((blk >> 6) + 2 * s) * 64;
            float acc[4][4] = {};
#pragma unroll 1
            for (int kc = 0; kc < 8; kc++) {
                cpa_wait0();
                __syncthreads();
                if (kc < 7)       { prefetch_a(sb, tid, m0, kc + 1, (kc + 1) & 1); cpa_commit(); }
                else if (s < 255) { prefetch_a(sb, tid, ((blk >> 6) + 2 * (s + 1)) * 64, 0, 0); cpa_commit(); }
                unsigned ab  = sb + B_ABASE + (unsigned)((kc & 1) * B_ABUF) + (unsigned)(rowA * 144) + koffA;
                unsigned kwb = (unsigned)(kc * 128);
#pragma unroll
                for (int ks = 0; ks < 4; ks++) {
                    unsigned ah[4], al[4], bh[8], bl[8];
                    ldsm4(ah, ab + ks * 32);
                    ldsm4(al, ab + 9216u + ks * 32);
                    ldsm4(bh,     wb0 + kwb + ks * 32);
                    ldsm4(bh + 4, wb1 + kwb + ks * 32);
                    ldsm4(bl,     wl0 + kwb + ks * 32);
                    ldsm4(bl + 4, wl1 + kwb + ks * 32);
#pragma unroll
                    for (int nt = 0; nt < 4; nt++) {
                        mma_acc(acc[nt], ah, bh[2 * nt], bh[2 * nt + 1]);
                        mma_acc(acc[nt], ah, bl[2 * nt], bl[2 * nt + 1]);
                        mma_acc(acc[nt], al, bh[2 * nt], bh[2 * nt + 1]);
                    }
                }
            }
#pragma unroll
            for (int nt = 0; nt < 4; nt++)
#pragma unroll
                for (int f = 0; f < 4; f++) {
                    int row = m0 + wm * 16 + gq + (f >> 1) * 8;
                    int cn  = n0 + wn * 32 + nt * 8 + 2 * tig + (f & 1);
                    g_zx[(size_t)row * G4 + cn] = acc[nt][f] + __ldg(&bk[cn]);
                }
        }
    }
    grid_bar(gen);

    // ===== Phase C: 256 recurrent steps (W resident, H streamed) =====
    {
        int4* sW4 = (int4*)smem;
        for (int i = tid; i < 64 * 128; i += NTHR) {
            int j = i >> 7, q = i & 127;
            sW4[j * 129 + q] = g_wpk4[((size_t)blk * 64 + j) * 128 + q];
        }
        const int l15 = lane & 15;
        const unsigned koffA = (unsigned)((lane >> 4) << 4);
        const unsigned bko   = (unsigned)(((lane >> 3) & 1) << 4);
        const int bn = (lane & 7) + ((lane >> 4) << 3);
        const unsigned wB0 = sb + (unsigned)(bn * 2064) + bko;
        const unsigned wB1 = wB0 + 16u * 2064u;
        const unsigned wL0 = wB0 + 32u * 2064u;
        const unsigned wL1 = wB0 + 48u * 2064u;
        const int rowA = wid * 16 + l15;

        __nv_bfloat16* hbh0 = (__nv_bfloat16*)g_hbhi4[0];
        __nv_bfloat16* hbh1 = (__nv_bfloat16*)g_hbhi4[1];
        __nv_bfloat16* hbl0 = (__nv_bfloat16*)g_hblo4[0];
        __nv_bfloat16* hbl1 = (__nv_bfloat16*)g_hblo4[1];

        float cst[4] = {0.f, 0.f, 0.f, 0.f};

        for (int t = 0; t < TT; t++) {
            const int p = t & 1;
            float zreg[16];
#pragma unroll
            for (int f = 0; f < 4; f++) {
                int b_ = wid * 16 + gq + (f >> 1) * 8;
                size_t zb = ((size_t)b_ * TT + t) * G4 + (blk << 3) + 2 * tig + (f & 1);
#pragma unroll
                for (int g = 0; g < 4; g++) zreg[f * 4 + g] = __ldcg(&g_zx[zb + (size_t)g * HH]);
            }
            prefetch_h(sb, tid, p, 0, 0);
            cpa_commit();
            float acc[4][4] = {};
#pragma unroll 1
            for (int kc = 0; kc < 16; kc++) {
                cpa_wait0();
                __syncthreads();
                if (kc < 15) { prefetch_h(sb, tid, p, kc + 1, (kc + 1) & 1); cpa_commit(); }
                unsigned hb  = sb + C_H0 + (unsigned)((kc & 1) * C_HBUF) + (unsigned)(rowA * 144) + koffA;
                unsigned kwb = (unsigned)(kc * 128);
#pragma unroll
                for (int ks = 0; ks < 4; ks++) {
                    unsigned ah[4], al[4], bh[8], bl[8];
                    ldsm4(ah, hb + ks * 32);
                    ldsm4(al, hb + 18432u + ks * 32);
                    ldsm4(bh,     wB0 + kwb + ks * 32);
                    ldsm4(bh + 4, wB1 + kwb + ks * 32);
                    ldsm4(bl,     wL0 + kwb + ks * 32);
                    ldsm4(bl + 4, wL1 + kwb + ks * 32);
#pragma unroll
                    for (int nt = 0; nt < 4; nt++) {
                        mma_acc(acc[nt], ah, bh[2 * nt], bh[2 * nt + 1]);
                        mma_acc(acc[nt], ah, bl[2 * nt], bl[2 * nt + 1]);
                        mma_acc(acc[nt], al, bh[2 * nt], bh[2 * nt + 1]);
                    }
                }
            }
#pragma unroll
            for (int f = 0; f < 4; f++) {
                float zi = acc[0][f] + zreg[f * 4 + 0];
                float zj = acc[1][f] + zreg[f * 4 + 1];
                float zf = acc[2][f] + zreg[f * 4 + 2];
                float zo = acc[3][f] + zreg[f * 4 + 3];
                float cn = cst[f] * sigmoidf_(zf + 1.0f) + sigmoidf_(zi) * tanhf(zj);
                float hn = sigmoidf_(zo) * tanhf(cn);
                cst[f] = cn;
                int b_ = wid * 16 + gq + (f >> 1) * 8;
                int hidx = b_ * HH + (blk << 3) + 2 * tig + (f & 1);
                __nv_bfloat16 bhv = __float2bfloat16_rn(hn);
                __nv_bfloat16 blv = __float2bfloat16_rn(hn - __bfloat162float(bhv));
                if (p) { hbh0[hidx] = bhv; hbl0[hidx] = blv; }
                else   { hbh1[hidx] = bhv; hbl1[hidx] = blv; }
                if (t == TT - 1) g_hT[hidx] = hn;
            }
            grid_bar(gen);
        }
    }

    // ===== Phase D: out = hT @ w + bo =====
    {
        float* sh = (float*)smem;
        const int b_ = blk;
        for (int k = tid; k < HH; k += NTHR) sh[k] = g_hT[b_ * HH + k];
        __syncthreads();
        for (int c = tid; c < CC; c += NTHR) {
            float acc = bo[c];
#pragma unroll 8
            for (int k = 0; k < HH; k++) acc = fmaf(sh[k], w[k * CC + c], acc);
            out[b_ * CC + c] = acc;
        }
    }
}

extern "C" void kernel_launch(void* const* d_in, const int* in_sizes, int n_in,
                              void* d_out, int out_size) {
    (void)in_sizes; (void)n_in; (void)out_size;
    const float* x  = (const float*)d_in[0];
    const float* Wk = (const float*)d_in[1];
    const float* bk = (const float*)d_in[2];
    const float* w  = (const float*)d_in[3];
    const float* b  = (const float*)d_in[4];
    float* out = (float*)d_out;
    cudaFuncSetAttribute(lstm_persistent, cudaFuncAttributeMaxDynamicSharedMemorySize, DYN_SMEM);
    lstm_persistent<<<NCTA, NTHR, DYN_SMEM>>>(x, Wk, bk, w, b, out);
}

// round 4
// speedup vs baseline: 1.6093x; 1.0750x over previous
#include <cuda_runtime.h>
#include <cuda_bf16.h>

#define BB   128
#define TT   256
#define DD   512
#define HH   1024
#define G4   4096
#define CC   1000
#define NCTA 128
#define NTHR 512

// dynamic smem layout (bytes)
#define C_H0    132096      // phase C: W resident [64 rows][2064B], then H bufs
#define C_HBUF  36864       // one H buf: hi 18432 + lo 18432
#define C_Z     205824      // z exchange buffer 128*33*4 = 16896
#define B_ABASE 133120      // phase B: B resident 2x66560, then A bufs
#define B_ABUF  18432
#define DYN_SMEM 222720

// ---------------- device scratch ----------------
__device__ float g_zx[(size_t)BB * TT * G4];
__device__ int4  g_xhi4[BB * TT * DD / 8];
__device__ int4  g_xlo4[BB * TT * DD / 8];
__device__ int4  g_wxhi4[DD * G4 / 8];                // TRANSPOSED [n:4096][k:512] bf16
__device__ int4  g_wxlo4[DD * G4 / 8];
__device__ int4  g_wpk4[(size_t)NCTA * 64 * HH / 8];  // [cta][j:64][k:1024] bf16
__device__ int4  g_hbhi4[2][BB * HH / 8];
__device__ int4  g_hblo4[2][BB * HH / 8];
__device__ float g_hT[BB * HH];
__device__ unsigned g_gen;
__device__ unsigned g_cnt;

__device__ __forceinline__ float sigmoid_fast(float x) {
    return __fdividef(1.0f, 1.0f + __expf(-x));
}
__device__ __forceinline__ float tanh_fast(float x) {
    float xc = fminf(fmaxf(x, -15.0f), 15.0f);
    float e = __expf(2.0f * xc);
    return __fdividef(e - 1.0f, e + 1.0f);
}

__device__ __forceinline__ void split_us(float v, unsigned short &h, unsigned short &l) {
    __nv_bfloat16 bh = __float2bfloat16_rn(v);
    float r = v - __bfloat162float(bh);
    h = __bfloat16_as_ushort(bh);
    l = __bfloat16_as_ushort(__float2bfloat16_rn(r));
}

__device__ __forceinline__ void mma_acc(float* c, const unsigned* a, unsigned b0, unsigned b1) {
    asm volatile(
        "mma.sync.aligned.m16n8k16.row.col.f32.bf16.bf16.f32 "
        "{%0,%1,%2,%3}, {%4,%5,%6,%7}, {%8,%9}, {%0,%1,%2,%3};\n"
        : "+f"(c[0]), "+f"(c[1]), "+f"(c[2]), "+f"(c[3])
        : "r"(a[0]), "r"(a[1]), "r"(a[2]), "r"(a[3]), "r"(b0), "r"(b1));
}

__device__ __forceinline__ void ldsm4(unsigned* r, unsigned a) {
    asm volatile("ldmatrix.sync.aligned.m8n8.x4.shared.b16 {%0,%1,%2,%3}, [%4];\n"
                 : "=r"(r[0]), "=r"(r[1]), "=r"(r[2]), "=r"(r[3]) : "r"(a));
}

__device__ __forceinline__ void cpa16(unsigned s, const void* g) {
    asm volatile("cp.async.cg.shared.global [%0], [%1], 16;\n" :: "r"(s), "l"(g) : "memory");
}
__device__ __forceinline__ void cpa_commit() { asm volatile("cp.async.commit_group;\n" ::: "memory"); }
__device__ __forceinline__ void cpa_wait0()  { asm volatile("cp.async.wait_group 0;\n" ::: "memory"); }

// grid barrier: leader-only gpu fences (bar.sync + cumulative leader fence)
__device__ __forceinline__ void grid_bar(unsigned &gen) {
    __syncthreads();
    if (threadIdx.x == 0) {
        __threadfence();
        if (atomicAdd(&g_cnt, 1u) == NCTA - 1u) {
            g_cnt = 0u;
            __threadfence();
            atomicExch(&g_gen, gen + 1u);
        } else {
            volatile unsigned* vg = &g_gen;
            while (*vg == gen) __nanosleep(64);
            __threadfence();
        }
    }
    __syncthreads();
    gen++;
}

__device__ __forceinline__ void prefetch_h(unsigned sb, int tid, int p, int kc, int buf) {
    unsigned dst = sb + C_H0 + (unsigned)(buf * C_HBUF);
    const int4* hi = g_hbhi4[p];
    const int4* lo = g_hblo4[p];
#pragma unroll
    for (int j2 = 0; j2 < 2; j2++) {
        int e = tid + j2 * 512;
        int row = e >> 3, q = e & 7;
        int gi = row * 128 + kc * 8 + q;
        cpa16(dst + (unsigned)(row * 144 + q * 16), hi + gi);
        cpa16(dst + 18432u + (unsigned)(row * 144 + q * 16), lo + gi);
    }
}

__device__ __forceinline__ void prefetch_a(unsigned sb, int tid, int m0, int kc, int buf) {
    unsigned dst = sb + B_ABASE + (unsigned)(buf * B_ABUF);
    int row = tid >> 3, q = tid & 7;
    int gi = (m0 + row) * 64 + kc * 8 + q;
    cpa16(dst + (unsigned)(row * 144 + q * 16), g_xhi4 + gi);
    cpa16(dst + 9216u + (unsigned)(row * 144 + q * 16), g_xlo4 + gi);
}

extern __shared__ __align__(16) unsigned char smem[];

__global__ void __launch_bounds__(NTHR, 1)
lstm_persistent(const float* __restrict__ x, const float* __restrict__ Wk,
                const float* __restrict__ bk, const float* __restrict__ w,
                const float* __restrict__ bo, float* __restrict__ out) {
    const int tid  = threadIdx.x;
    const int blk  = blockIdx.x;
    const int wid  = tid >> 5;
    const int lane = tid & 31;
    const int gq   = lane >> 2;
    const int tig  = lane & 3;
    const unsigned sb = (unsigned)__cvta_generic_to_shared(smem);

    unsigned gen = atomicAdd(&g_gen, 0u);

    const int gtid = blk * NTHR + tid;
    const int gstr = NCTA * NTHR;

    // ===== Phase A: precision splits + repacks =====
    {
        const float4* x4 = (const float4*)x;
        ushort4* xh = (ushort4*)g_xhi4;
        ushort4* xl = (ushort4*)g_xlo4;
        for (int i = gtid; i < BB * TT * DD / 4; i += gstr) {
            float4 v = x4[i];
            ushort4 h, l;
            split_us(v.x, h.x, l.x); split_us(v.y, h.y, l.y);
            split_us(v.z, h.z, l.z); split_us(v.w, h.w, l.w);
            xh[i] = h; xl[i] = l;
        }
        unsigned short* wth = (unsigned short*)g_wxhi4;
        unsigned short* wtl = (unsigned short*)g_wxlo4;
        for (int i = gtid; i < G4 * DD; i += gstr) {
            int n = i >> 9, k = i & 511;
            float v = Wk[(size_t)k * G4 + n];
            unsigned short h, l;
            split_us(v, h, l);
            wth[i] = h; wtl[i] = l;
        }
        unsigned short* wpk = (unsigned short*)g_wpk4;
        for (int i = gtid; i < NCTA * 64 * HH; i += gstr) {
            int k  = i & (HH - 1);
            int j  = (i >> 10) & 63;
            int bq = i >> 16;
            int lc = j & 31, part = j >> 5;
            int col = ((lc >> 3) << 10) + (bq << 3) + (lc & 7);
            float v = Wk[(size_t)(DD + k) * G4 + col];
            __nv_bfloat16 bh = __float2bfloat16_rn(v);
            unsigned short us = part
                ? __bfloat16_as_ushort(__float2bfloat16_rn(v - __bfloat162float(bh)))
                : __bfloat16_as_ushort(bh);
            wpk[i] = us;
        }
        int4 z4 = make_int4(0, 0, 0, 0);
        for (int i = gtid; i < BB * HH / 8; i += gstr) {
            g_hbhi4[0][i] = z4; g_hbhi4[1][i] = z4;
            g_hblo4[0][i] = z4; g_hblo4[1][i] = z4;
        }
    }
    grid_bar(gen);

    // ===== Phase B: Zx = x @ Wx + bk  (B slab resident, A streamed) =====
    {
        const int n0 = (blk & 63) * 64;
        int4* sB4 = (int4*)smem;
        for (int i = tid; i < 64 * 64; i += NTHR) {
            int r = i >> 6, q = i & 63;
            sB4[r * 65 + q]        = g_wxhi4[(n0 + r) * 64 + q];
            sB4[4160 + r * 65 + q] = g_wxlo4[(n0 + r) * 64 + q];
        }
        const int wm = wid & 3, wn = wid >> 2;
        const int l15 = lane & 15;
        const unsigned koffA = (unsigned)((lane >> 4) << 4);
        const unsigned bko   = (unsigned)(((lane >> 3) & 1) << 4);
        const int bn = (lane & 7) + ((lane >> 4) << 3);
        const int rowA = wm * 16 + l15;
        const unsigned wb0 = sb + (unsigned)((wn * 16 + bn) * 1040) + bko;
        const unsigned wl0 = wb0 + 66560u;

        prefetch_a(sb, tid, (blk >> 6) * 64, 0, 0);
        cpa_commit();
        for (int s = 0; s < 256; s++) {
            const int m0 = ((blk >> 6) + 2 * s) * 64;
            float acc[2][4] = {};
#pragma unroll 1
            for (int kc = 0; kc < 8; kc++) {
                cpa_wait0();
                __syncthreads();
                if (kc < 7)       { prefetch_a(sb, tid, m0, kc + 1, (kc + 1) & 1); cpa_commit(); }
                else if (s < 255) { prefetch_a(sb, tid, ((blk >> 6) + 2 * (s + 1)) * 64, 0, 0); cpa_commit(); }
                unsigned ab  = sb + B_ABASE + (unsigned)((kc & 1) * B_ABUF) + (unsigned)(rowA * 144) + koffA;
                unsigned kwb = (unsigned)(kc * 128);
#pragma unroll
                for (int ks = 0; ks < 4; ks++) {
                    unsigned ah[4], al[4], bh[4], bl[4];
                    ldsm4(ah, ab + ks * 32);
                    ldsm4(al, ab + 9216u + ks * 32);
                    ldsm4(bh, wb0 + kwb + ks * 32);
                    ldsm4(bl, wl0 + kwb + ks * 32);
#pragma unroll
                    for (int nt = 0; nt < 2; nt++) {
                        mma_acc(acc[nt], ah, bh[2 * nt], bh[2 * nt + 1]);
                        mma_acc(acc[nt], ah, bl[2 * nt], bl[2 * nt + 1]);
                        mma_acc(acc[nt], al, bh[2 * nt], bh[2 * nt + 1]);
                    }
                }
            }
#pragma unroll
            for (int nt = 0; nt < 2; nt++)
#pragma unroll
                for (int f = 0; f < 4; f++) {
                    int row = m0 + wm * 16 + gq + (f >> 1) * 8;
                    int cn  = n0 + wn * 16 + nt * 8 + 2 * tig + (f & 1);
                    g_zx[(size_t)row * G4 + cn] = acc[nt][f] + __ldg(&bk[cn]);
                }
        }
    }
    grid_bar(gen);

    // ===== Phase C: 256 recurrent steps (W resident, H streamed) =====
    {
        int4* sW4 = (int4*)smem;
        for (int i = tid; i < 64 * 128; i += NTHR) {
            int j = i >> 7, q = i & 127;
            sW4[j * 129 + q] = g_wpk4[((size_t)blk * 64 + j) * 128 + q];
        }
        const int wm = wid & 7, wn = wid >> 3;
        const int l15 = lane & 15;
        const unsigned koffA = (unsigned)((lane >> 4) << 4);
        const unsigned bko   = (unsigned)(((lane >> 3) & 1) << 4);
        const int bn = (lane & 7) + ((lane >> 4) << 3);
        const unsigned wB0 = sb + (unsigned)((wn * 16 + bn) * 2064) + bko;
        const unsigned wL0 = wB0 + 32u * 2064u;
        const int rowA = wm * 16 + l15;
        float* zs = (float*)(smem + C_Z);

        __nv_bfloat16* hbh0 = (__nv_bfloat16*)g_hbhi4[0];
        __nv_bfloat16* hbh1 = (__nv_bfloat16*)g_hbhi4[1];
        __nv_bfloat16* hbl0 = (__nv_bfloat16*)g_hblo4[0];
        __nv_bfloat16* hbl1 = (__nv_bfloat16*)g_hblo4[1];

        const int gb = tid >> 2;          // batch row owned in epilogue
        const int u0 = (tid & 3) << 1;    // first of 2 hidden units
        float cst[2] = {0.f, 0.f};

        for (int t = 0; t < TT; t++) {
            const int p = t & 1;
            float zxr[2][4];
#pragma unroll
            for (int uu = 0; uu < 2; uu++) {
                size_t zb = ((size_t)gb * TT + t) * G4 + (blk << 3) + u0 + uu;
#pragma unroll
                for (int g = 0; g < 4; g++) zxr[uu][g] = __ldcg(&g_zx[zb + (size_t)g * HH]);
            }
            prefetch_h(sb, tid, p, 0, 0);
            cpa_commit();
            float acc[2][4] = {};
#pragma unroll 1
            for (int kc = 0; kc < 16; kc++) {
                cpa_wait0();
                __syncthreads();
                if (kc < 15) { prefetch_h(sb, tid, p, kc + 1, (kc + 1) & 1); cpa_commit(); }
                unsigned hb  = sb + C_H0 + (unsigned)((kc & 1) * C_HBUF) + (unsigned)(rowA * 144) + koffA;
                unsigned kwb = (unsigned)(kc * 128);
#pragma unroll
                for (int ks = 0; ks < 4; ks++) {
                    unsigned ah[4], al[4], bh[4], bl[4];
                    ldsm4(ah, hb + ks * 32);
                    ldsm4(al, hb + 18432u + ks * 32);
                    ldsm4(bh, wB0 + kwb + ks * 32);
                    ldsm4(bl, wL0 + kwb + ks * 32);
#pragma unroll
                    for (int nt = 0; nt < 2; nt++) {
                        mma_acc(acc[nt], ah, bh[2 * nt], bh[2 * nt + 1]);
                        mma_acc(acc[nt], ah, bl[2 * nt], bl[2 * nt + 1]);
                        mma_acc(acc[nt], al, bh[2 * nt], bh[2 * nt + 1]);
                    }
                }
            }
            // exchange partial z through smem (gates live in different warps)
#pragma unroll
            for (int nt = 0; nt < 2; nt++)
#pragma unroll
                for (int f = 0; f < 4; f++) {
                    int row = wm * 16 + gq + (f >> 1) * 8;
                    int col = wn * 16 + nt * 8 + 2 * tig + (f & 1);
                    zs[row * 33 + col] = acc[nt][f];
                }
            __syncthreads();
            // gate math: thread owns (batch row gb, units u0..u0+1)
#pragma unroll
            for (int uu = 0; uu < 2; uu++) {
                int u = u0 + uu;
                float zi = zs[gb * 33 + 0 * 8 + u] + zxr[uu][0];
                float zj = zs[gb * 33 + 1 * 8 + u] + zxr[uu][1];
                float zf = zs[gb * 33 + 2 * 8 + u] + zxr[uu][2];
                float zo = zs[gb * 33 + 3 * 8 + u] + zxr[uu][3];
                float cn = cst[uu] * sigmoid_fast(zf + 1.0f) + sigmoid_fast(zi) * tanh_fast(zj);
                float hn = sigmoid_fast(zo) * tanh_fast(cn);
                cst[uu] = cn;
                int hidx = gb * HH + (blk << 3) + u;
                __nv_bfloat16 bhv = __float2bfloat16_rn(hn);
                __nv_bfloat16 blv = __float2bfloat16_rn(hn - __bfloat162float(bhv));
                if (p) { hbh0[hidx] = bhv; hbl0[hidx] = blv; }
                else   { hbh1[hidx] = bhv; hbl1[hidx] = blv; }
                if (t == TT - 1) g_hT[hidx] = hn;
            }
            grid_bar(gen);
        }
    }

    // ===== Phase D: out = hT @ w + bo =====
    {
        float* sh = (float*)smem;
        const int b_ = blk;
        for (int k = tid; k < HH; k += NTHR) sh[k] = g_hT[b_ * HH + k];
        __syncthreads();
        for (int c = tid; c < CC; c += NTHR) {
            float acc = bo[c];
#pragma unroll 8
            for (int k = 0; k < HH; k++) acc = fmaf(sh[k], w[k * CC + c], acc);
            out[b_ * CC + c] = acc;
        }
    }
}

extern "C" void kernel_launch(void* const* d_in, const int* in_sizes, int n_in,
                              void* d_out, int out_size) {
    (void)in_sizes; (void)n_in; (void)out_size;
    const float* x  = (const float*)d_in[0];
    const float* Wk = (const float*)d_in[1];
    const float* bk = (const float*)d_in[2];
    const float* w  = (const float*)d_in[3];
    const float* b  = (const float*)d_in[4];
    float* out = (float*)d_out;
    cudaFuncSetAttribute(lstm_persistent, cudaFuncAttributeMaxDynamicSharedMemorySize, DYN_SMEM);
    lstm_persistent<<<NCTA, NTHR, DYN_SMEM>>>(x, Wk, bk, w, b, out);
}

// round 6
// speedup vs baseline: 1.8699x; 1.1619x over previous
#include <cuda_runtime.h>
#include <cuda_bf16.h>
#include <cuda_fp16.h>

#define BB   128
#define TT   256
#define DD   512
#define HH   1024
#define G4   4096
#define CC   1000
#define NCTA 128
#define NTHR 512

// dynamic smem layout (bytes)
#define C_H0    132096      // phase C: W resident [64 rows][2064B], then H bufs
#define C_HBUF  18432       // one H buf (fp16 hi only): 128 rows x 144B
#define C_Z     168960      // z exchange buffer 128*33*4 = 16896
#define B_ABASE 133120      // phase B: B resident 2x66560, then A bufs
#define B_ABUF  18432
#define DYN_SMEM 185856

// ---------------- device scratch ----------------
__device__ float g_zx[(size_t)BB * TT * G4];
__device__ int4  g_xhi4[BB * TT * DD / 8];
__device__ int4  g_xlo4[BB * TT * DD / 8];
__device__ int4  g_wxhi4[DD * G4 / 8];                // TRANSPOSED [n:4096][k:512] bf16
__device__ int4  g_wxlo4[DD * G4 / 8];
__device__ int4  g_wpk4[(size_t)NCTA * 64 * HH / 8];  // [cta][j:64][k:1024] fp16 (hi rows 0-31, lo rows 32-63)
__device__ int4  g_hb4[2][BB * HH / 8];               // h fp16, double buffered
__device__ float g_hT[BB * HH];
__device__ unsigned g_gen;
__device__ unsigned g_cnt;

__device__ __forceinline__ float sigmoid_fast(float x) {
    return __fdividef(1.0f, 1.0f + __expf(-x));
}
__device__ __forceinline__ float tanh_fast(float x) {
    float xc = fminf(fmaxf(x, -15.0f), 15.0f);
    float e = __expf(2.0f * xc);
    return __fdividef(e - 1.0f, e + 1.0f);
}

__device__ __forceinline__ void split_us(float v, unsigned short &h, unsigned short &l) {
    __nv_bfloat16 bh = __float2bfloat16_rn(v);
    float r = v - __bfloat162float(bh);
    h = __bfloat16_as_ushort(bh);
    l = __bfloat16_as_ushort(__float2bfloat16_rn(r));
}

// bf16 mma (phase B)
__device__ __forceinline__ void mma_acc(float* c, const unsigned* a, unsigned b0, unsigned b1) {
    asm volatile(
        "mma.sync.aligned.m16n8k16.row.col.f32.bf16.bf16.f32 "
        "{%0,%1,%2,%3}, {%4,%5,%6,%7}, {%8,%9}, {%0,%1,%2,%3};\n"
        : "+f"(c[0]), "+f"(c[1]), "+f"(c[2]), "+f"(c[3])
        : "r"(a[0]), "r"(a[1]), "r"(a[2]), "r"(a[3]), "r"(b0), "r"(b1));
}
// fp16 mma (phase C)
__device__ __forceinline__ void mma_f16(float* c, const unsigned* a, unsigned b0, unsigned b1) {
    asm volatile(
        "mma.sync.aligned.m16n8k16.row.col.f32.f16.f16.f32 "
        "{%0,%1,%2,%3}, {%4,%5,%6,%7}, {%8,%9}, {%0,%1,%2,%3};\n"
        : "+f"(c[0]), "+f"(c[1]), "+f"(c[2]), "+f"(c[3])
        : "r"(a[0]), "r"(a[1]), "r"(a[2]), "r"(a[3]), "r"(b0), "r"(b1));
}
__device__ __forceinline__ void ldsm4(unsigned* r, unsigned a) {
    asm volatile("ldmatrix.sync.aligned.m8n8.x4.shared.b16 {%0,%1,%2,%3}, [%4];\n"
                 : "=r"(r[0]), "=r"(r[1]), "=r"(r[2]), "=r"(r[3]) : "r"(a));
}

__device__ __forceinline__ void cpa16(unsigned s, const void* g) {
    asm volatile("cp.async.cg.shared.global [%0], [%1], 16;\n" :: "r"(s), "l"(g) : "memory");
}
__device__ __forceinline__ void cpa_commit() { asm volatile("cp.async.commit_group;\n" ::: "memory"); }
__device__ __forceinline__ void cpa_wait0()  { asm volatile("cp.async.wait_group 0;\n" ::: "memory"); }

// grid barrier: leader-only gpu fences
__device__ __forceinline__ void grid_bar(unsigned &gen) {
    __syncthreads();
    if (threadIdx.x == 0) {
        __threadfence();
        if (atomicAdd(&g_cnt, 1u) == NCTA - 1u) {
            g_cnt = 0u;
            __threadfence();
            atomicExch(&g_gen, gen + 1u);
        } else {
            volatile unsigned* vg = &g_gen;
            while (*vg == gen) __nanosleep(64);
            __threadfence();
        }
    }
    __syncthreads();
    gen++;
}

// phase C H-chunk loader (fp16 hi only)
__device__ __forceinline__ void prefetch_h(unsigned sb, int tid, int p, int kc, int buf) {
    unsigned dst = sb + C_H0 + (unsigned)(buf * C_HBUF);
    const int4* hp = g_hb4[p];
#pragma unroll
    for (int j2 = 0; j2 < 2; j2++) {
        int e = tid + j2 * 512;
        int row = e >> 3, q = e & 7;
        int gi = row * 128 + kc * 8 + q;
        cpa16(dst + (unsigned)(row * 144 + q * 16), hp + gi);
    }
}

// phase B A-chunk loader
__device__ __forceinline__ void prefetch_a(unsigned sb, int tid, int m0, int kc, int buf) {
    unsigned dst = sb + B_ABASE + (unsigned)(buf * B_ABUF);
    int row = tid >> 3, q = tid & 7;
    int gi = (m0 + row) * 64 + kc * 8 + q;
    cpa16(dst + (unsigned)(row * 144 + q * 16), g_xhi4 + gi);
    cpa16(dst + 9216u + (unsigned)(row * 144 + q * 16), g_xlo4 + gi);
}

extern __shared__ __align__(16) unsigned char smem[];

__global__ void __launch_bounds__(NTHR, 1)
lstm_persistent(const float* __restrict__ x, const float* __restrict__ Wk,
                const float* __restrict__ bk, const float* __restrict__ w,
                const float* __restrict__ bo, float* __restrict__ out) {
    const int tid  = threadIdx.x;
    const int blk  = blockIdx.x;
    const int wid  = tid >> 5;
    const int lane = tid & 31;
    const int gq   = lane >> 2;
    const int tig  = lane & 3;
    const unsigned sb = (unsigned)__cvta_generic_to_shared(smem);

    unsigned gen = atomicAdd(&g_gen, 0u);

    const int gtid = blk * NTHR + tid;
    const int gstr = NCTA * NTHR;

    // ===== Phase A: precision splits + repacks =====
    {
        const float4* x4 = (const float4*)x;
        ushort4* xh = (ushort4*)g_xhi4;
        ushort4* xl = (ushort4*)g_xlo4;
        for (int i = gtid; i < BB * TT * DD / 4; i += gstr) {
            float4 v = x4[i];
            ushort4 h, l;
            split_us(v.x, h.x, l.x); split_us(v.y, h.y, l.y);
            split_us(v.z, h.z, l.z); split_us(v.w, h.w, l.w);
            xh[i] = h; xl[i] = l;
        }
        unsigned short* wth = (unsigned short*)g_wxhi4;
        unsigned short* wtl = (unsigned short*)g_wxlo4;
        for (int i = gtid; i < G4 * DD; i += gstr) {
            int n = i >> 9, k = i & 511;
            float v = Wk[(size_t)k * G4 + n];
            unsigned short h, l;
            split_us(v, h, l);
            wth[i] = h; wtl[i] = l;
        }
        // Wh repack per CTA, gate-gathered, fp16 hi (rows 0-31) / fp16 lo (rows 32-63)
        unsigned short* wpk = (unsigned short*)g_wpk4;
        for (int i = gtid; i < NCTA * 64 * HH; i += gstr) {
            int k  = i & (HH - 1);
            int j  = (i >> 10) & 63;
            int bq = i >> 16;
            int lc = j & 31, part = j >> 5;
            int col = ((lc >> 3) << 10) + (bq << 3) + (lc & 7);
            float v = Wk[(size_t)(DD + k) * G4 + col];
            __half hh = __float2half_rn(v);
            unsigned short us = part
                ? __half_as_ushort(__float2half_rn(v - __half2float(hh)))
                : __half_as_ushort(hh);
            wpk[i] = us;
        }
        int4 z4 = make_int4(0, 0, 0, 0);
        for (int i = gtid; i < BB * HH / 8; i += gstr) {
            g_hb4[0][i] = z4; g_hb4[1][i] = z4;
        }
    }
    grid_bar(gen);

    // ===== Phase B: Zx = x @ Wx + bk  (bf16 3-term, B slab resident, A streamed) =====
    {
        const int n0 = (blk & 63) * 64;
        int4* sB4 = (int4*)smem;
        for (int i = tid; i < 64 * 64; i += NTHR) {
            int r = i >> 6, q = i & 63;
            sB4[r * 65 + q]        = g_wxhi4[(n0 + r) * 64 + q];
            sB4[4160 + r * 65 + q] = g_wxlo4[(n0 + r) * 64 + q];
        }
        const int wm = wid & 3, wn = wid >> 2;
        const int l15 = lane & 15;
        const unsigned koffA = (unsigned)((lane >> 4) << 4);
        const unsigned bko   = (unsigned)(((lane >> 3) & 1) << 4);
        const int bn = (lane & 7) + ((lane >> 4) << 3);
        const int rowA = wm * 16 + l15;
        const unsigned wb0 = sb + (unsigned)((wn * 16 + bn) * 1040) + bko;
        const unsigned wl0 = wb0 + 66560u;

        prefetch_a(sb, tid, (blk >> 6) * 64, 0, 0);
        cpa_commit();
        for (int s = 0; s < 256; s++) {
            const int m0 = ((blk >> 6) + 2 * s) * 64;
            float acc[2][4] = {};
#pragma unroll 1
            for (int kc = 0; kc < 8; kc++) {
                cpa_wait0();
                __syncthreads();
                if (kc < 7)       { prefetch_a(sb, tid, m0, kc + 1, (kc + 1) & 1); cpa_commit(); }
                else if (s < 255) { prefetch_a(sb, tid, ((blk >> 6) + 2 * (s + 1)) * 64, 0, 0); cpa_commit(); }
                unsigned ab  = sb + B_ABASE + (unsigned)((kc & 1) * B_ABUF) + (unsigned)(rowA * 144) + koffA;
                unsigned kwb = (unsigned)(kc * 128);
#pragma unroll
                for (int ks = 0; ks < 4; ks++) {
                    unsigned ah[4], al[4], bh[4], bl[4];
                    ldsm4(ah, ab + ks * 32);
                    ldsm4(al, ab + 9216u + ks * 32);
                    ldsm4(bh, wb0 + kwb + ks * 32);
                    ldsm4(bl, wl0 + kwb + ks * 32);
#pragma unroll
                    for (int nt = 0; nt < 2; nt++) {
                        mma_acc(acc[nt], ah, bh[2 * nt], bh[2 * nt + 1]);
                        mma_acc(acc[nt], ah, bl[2 * nt], bl[2 * nt + 1]);
                        mma_acc(acc[nt], al, bh[2 * nt], bh[2 * nt + 1]);
                    }
                }
            }
#pragma unroll
            for (int nt = 0; nt < 2; nt++)
#pragma unroll
                for (int f = 0; f < 4; f++) {
                    int row = m0 + wm * 16 + gq + (f >> 1) * 8;
                    int cn  = n0 + wn * 16 + nt * 8 + 2 * tig + (f & 1);
                    g_zx[(size_t)row * G4 + cn] = acc[nt][f] + __ldg(&bk[cn]);
                }
        }
    }
    grid_bar(gen);

    // ===== Phase C: 256 recurrent steps (fp16: W hi+lo resident, h hi streamed) =====
    {
        int4* sW4 = (int4*)smem;
        for (int i = tid; i < 64 * 128; i += NTHR) {
            int j = i >> 7, q = i & 127;
            sW4[j * 129 + q] = g_wpk4[((size_t)blk * 64 + j) * 128 + q];
        }
        const int wm = wid & 7, wn = wid >> 3;
        const int l15 = lane & 15;
        const unsigned koffA = (unsigned)((lane >> 4) << 4);
        const unsigned bko   = (unsigned)(((lane >> 3) & 1) << 4);
        const int bn = (lane & 7) + ((lane >> 4) << 3);
        const unsigned wB0 = sb + (unsigned)((wn * 16 + bn) * 2064) + bko;
        const unsigned wL0 = wB0 + 32u * 2064u;
        const int rowA = wm * 16 + l15;
        float* zs = (float*)(smem + C_Z);

        __half* hb0 = (__half*)g_hb4[0];
        __half* hb1 = (__half*)g_hb4[1];

        const int gb = tid >> 2;          // batch row owned in epilogue
        const int u0 = (tid & 3) << 1;    // first of 2 hidden units
        float cst[2] = {0.f, 0.f};

        for (int t = 0; t < TT; t++) {
            const int p = t & 1;
            float zxr[2][4];
#pragma unroll
            for (int uu = 0; uu < 2; uu++) {
                size_t zb = ((size_t)gb * TT + t) * G4 + (blk << 3) + u0 + uu;
#pragma unroll
                for (int g = 0; g < 4; g++) zxr[uu][g] = __ldcg(&g_zx[zb + (size_t)g * HH]);
            }
            prefetch_h(sb, tid, p, 0, 0);
            cpa_commit();
            float acc[2][4] = {};
#pragma unroll 1
            for (int kc = 0; kc < 16; kc++) {
                cpa_wait0();
                __syncthreads();
                if (kc < 15) { prefetch_h(sb, tid, p, kc + 1, (kc + 1) & 1); cpa_commit(); }
                unsigned hbuf = sb + C_H0 + (unsigned)((kc & 1) * C_HBUF) + (unsigned)(rowA * 144) + koffA;
                unsigned kwb  = (unsigned)(kc * 128);
#pragma unroll
                for (int ks = 0; ks < 4; ks++) {
                    unsigned ah[4], bh[4], bl[4];
                    ldsm4(ah, hbuf + ks * 32);
                    ldsm4(bh, wB0 + kwb + ks * 32);
                    ldsm4(bl, wL0 + kwb + ks * 32);
#pragma unroll
                    for (int nt = 0; nt < 2; nt++) {
                        mma_f16(acc[nt], ah, bh[2 * nt], bh[2 * nt + 1]);
                        mma_f16(acc[nt], ah, bl[2 * nt], bl[2 * nt + 1]);
                    }
                }
            }
            // exchange partial z through smem (gates live in different warps)
#pragma unroll
            for (int nt = 0; nt < 2; nt++)
#pragma unroll
                for (int f = 0; f < 4; f++) {
                    int row = wm * 16 + gq + (f >> 1) * 8;
                    int col = wn * 16 + nt * 8 + 2 * tig + (f & 1);
                    zs[row * 33 + col] = acc[nt][f];
                }
            __syncthreads();
            // gate math: thread owns (batch row gb, units u0..u0+1)
#pragma unroll
            for (int uu = 0; uu < 2; uu++) {
                int u = u0 + uu;
                float zi = zs[gb * 33 + 0 * 8 + u] + zxr[uu][0];
                float zj = zs[gb * 33 + 1 * 8 + u] + zxr[uu][1];
                float zf = zs[gb * 33 + 2 * 8 + u] + zxr[uu][2];
                float zo = zs[gb * 33 + 3 * 8 + u] + zxr[uu][3];
                float cn = cst[uu] * sigmoid_fast(zf + 1.0f) + sigmoid_fast(zi) * tanh_fast(zj);
                float hn = sigmoid_fast(zo) * tanh_fast(cn);
                cst[uu] = cn;
                int hidx = gb * HH + (blk << 3) + u;
                __half hv = __float2half_rn(hn);
                if (p) hb0[hidx] = hv; else hb1[hidx] = hv;
                if (t == TT - 1) g_hT[hidx] = hn;
            }
            grid_bar(gen);
        }
    }

    // ===== Phase D: out = hT @ w + bo =====
    {
        float* sh = (float*)smem;
        const int b_ = blk;
        for (int k = tid; k < HH; k += NTHR) sh[k] = g_hT[b_ * HH + k];
        __syncthreads();
        for (int c = tid; c < CC; c += NTHR) {
            float acc = bo[c];
#pragma unroll 8
            for (int k = 0; k < HH; k++) acc = fmaf(sh[k], w[k * CC + c], acc);
            out[b_ * CC + c] = acc;
        }
    }
}

extern "C" void kernel_launch(void* const* d_in, const int* in_sizes, int n_in,
                              void* d_out, int out_size) {
    (void)in_sizes; (void)n_in; (void)out_size;
    const float* x  = (const float*)d_in[0];
    const float* Wk = (const float*)d_in[1];
    const float* bk = (const float*)d_in[2];
    const float* w  = (const float*)d_in[3];
    const float* b  = (const float*)d_in[4];
    float* out = (float*)d_out;
    cudaFuncSetAttribute(lstm_persistent, cudaFuncAttributeMaxDynamicSharedMemorySize, DYN_SMEM);
    lstm_persistent<<<NCTA, NTHR, DYN_SMEM>>>(x, Wk, bk, w, b, out);
}

// round 7
// speedup vs baseline: 2.2592x; 1.2082x over previous
#include <cuda_runtime.h>
#include <cuda_fp16.h>

#define BB   128
#define TT   256
#define DD   512
#define HH   1024
#define G4   4096
#define CC   1000
#define NCTA 128
#define NTHR 512

// dynamic smem layout (bytes)
// phase C: W slab [32 rows][2064B] = 66048, H bufs 2 x (128 rows x 272B), zs
#define C_H0    66560
#define C_HBUF  34816
#define C_Z     136192      // 128*33*4 = 16896
// phase B: Wx slab [64 rows][1040B] = 66560, A bufs 2 x (64 rows x 144B)
#define B_ABASE 66560
#define B_ABUF  9216
#define DYN_SMEM 153088

// ---------------- device scratch ----------------
__device__ float g_zx[(size_t)BB * TT * G4];
__device__ int4  g_x4[BB * TT * DD / 8];              // x fp16 [row][k:512]
__device__ int4  g_wx4[DD * G4 / 8];                  // Wx fp16 TRANSPOSED [n:4096][k:512]
__device__ int4  g_wpk4[(size_t)NCTA * 32 * HH / 8];  // Wh fp16 [cta][j:32][k:1024]
__device__ int4  g_hb4[2][BB * HH / 8];               // h fp16, double buffered
__device__ float g_hT[BB * HH];
__device__ unsigned g_gen;
__device__ unsigned g_cnt;

__device__ __forceinline__ float sigmoid_fast(float x) {
    return __fdividef(1.0f, 1.0f + __expf(-x));
}
__device__ __forceinline__ float tanh_fast(float x) {
    float xc = fminf(fmaxf(x, -15.0f), 15.0f);
    float e = __expf(2.0f * xc);
    return __fdividef(e - 1.0f, e + 1.0f);
}

// fp16 mma
__device__ __forceinline__ void mma_f16(float* c, const unsigned* a, unsigned b0, unsigned b1) {
    asm volatile(
        "mma.sync.aligned.m16n8k16.row.col.f32.f16.f16.f32 "
        "{%0,%1,%2,%3}, {%4,%5,%6,%7}, {%8,%9}, {%0,%1,%2,%3};\n"
        : "+f"(c[0]), "+f"(c[1]), "+f"(c[2]), "+f"(c[3])
        : "r"(a[0]), "r"(a[1]), "r"(a[2]), "r"(a[3]), "r"(b0), "r"(b1));
}
__device__ __forceinline__ void ldsm4(unsigned* r, unsigned a) {
    asm volatile("ldmatrix.sync.aligned.m8n8.x4.shared.b16 {%0,%1,%2,%3}, [%4];\n"
                 : "=r"(r[0]), "=r"(r[1]), "=r"(r[2]), "=r"(r[3]) : "r"(a));
}

__device__ __forceinline__ void cpa16(unsigned s, const void* g) {
    asm volatile("cp.async.cg.shared.global [%0], [%1], 16;\n" :: "r"(s), "l"(g) : "memory");
}
__device__ __forceinline__ void cpa_commit() { asm volatile("cp.async.commit_group;\n" ::: "memory"); }
__device__ __forceinline__ void cpa_wait0()  { asm volatile("cp.async.wait_group 0;\n" ::: "memory"); }

// grid barrier: leader-only gpu fences
__device__ __forceinline__ void grid_bar(unsigned &gen) {
    __syncthreads();
    if (threadIdx.x == 0) {
        __threadfence();
        if (atomicAdd(&g_cnt, 1u) == NCTA - 1u) {
            g_cnt = 0u;
            __threadfence();
            atomicExch(&g_gen, gen + 1u);
        } else {
            volatile unsigned* vg = &g_gen;
            while (*vg == gen) __nanosleep(64);
            __threadfence();
        }
    }
    __syncthreads();
    gen++;
}

// phase C H-chunk loader: chunk = 128 k (16 int4 per row), row stride 272B
__device__ __forceinline__ void prefetch_h(unsigned sb, int tid, int p, int kc, int buf) {
    unsigned dst = sb + C_H0 + (unsigned)(buf * C_HBUF);
    const int4* hp = g_hb4[p];
#pragma unroll
    for (int j2 = 0; j2 < 4; j2++) {
        int e = tid + j2 * 512;              // 0..2047
        int row = e >> 4, q = e & 15;
        int gi = row * 128 + kc * 16 + q;
        cpa16(dst + (unsigned)(row * 272 + q * 16), hp + gi);
    }
}

// phase B A-chunk loader: 64 rows x 8 int4, row stride 144B
__device__ __forceinline__ void prefetch_a(unsigned sb, int tid, int m0, int kc, int buf) {
    unsigned dst = sb + B_ABASE + (unsigned)(buf * B_ABUF);
    int row = tid >> 3, q = tid & 7;
    int gi = (m0 + row) * 64 + kc * 8 + q;
    cpa16(dst + (unsigned)(row * 144 + q * 16), g_x4 + gi);
}

extern __shared__ __align__(16) unsigned char smem[];

__global__ void __launch_bounds__(NTHR, 1)
lstm_persistent(const float* __restrict__ x, const float* __restrict__ Wk,
                const float* __restrict__ bk, const float* __restrict__ w,
                const float* __restrict__ bo, float* __restrict__ out) {
    const int tid  = threadIdx.x;
    const int blk  = blockIdx.x;
    const int wid  = tid >> 5;
    const int lane = tid & 31;
    const int gq   = lane >> 2;
    const int tig  = lane & 3;
    const unsigned sb = (unsigned)__cvta_generic_to_shared(smem);

    unsigned gen = atomicAdd(&g_gen, 0u);

    const int gtid = blk * NTHR + tid;
    const int gstr = NCTA * NTHR;

    // ===== Phase A: fp16 conversions + repacks =====
    {
        const float4* x4 = (const float4*)x;
        ushort4* xo = (ushort4*)g_x4;
        for (int i = gtid; i < BB * TT * DD / 4; i += gstr) {
            float4 v = x4[i];
            ushort4 h;
            h.x = __half_as_ushort(__float2half_rn(v.x));
            h.y = __half_as_ushort(__float2half_rn(v.y));
            h.z = __half_as_ushort(__float2half_rn(v.z));
            h.w = __half_as_ushort(__float2half_rn(v.w));
            xo[i] = h;
        }
        unsigned short* wt = (unsigned short*)g_wx4;
        for (int i = gtid; i < G4 * DD; i += gstr) {
            int n = i >> 9, k = i & 511;
            wt[i] = __half_as_ushort(__float2half_rn(Wk[(size_t)k * G4 + n]));
        }
        // Wh repack per CTA, gate-gathered, fp16
        unsigned short* wpk = (unsigned short*)g_wpk4;
        for (int i = gtid; i < NCTA * 32 * HH; i += gstr) {
            int k  = i & (HH - 1);
            int j  = (i >> 10) & 31;
            int bq = i >> 15;
            int col = ((j >> 3) << 10) + (bq << 3) + (j & 7);
            wpk[i] = __half_as_ushort(__float2half_rn(Wk[(size_t)(DD + k) * G4 + col]));
        }
        int4 z4 = make_int4(0, 0, 0, 0);
        for (int i = gtid; i < BB * HH / 8; i += gstr) {
            g_hb4[0][i] = z4; g_hb4[1][i] = z4;
        }
    }
    grid_bar(gen);

    // ===== Phase B: Zx = x @ Wx + bk  (fp16 single-term) =====
    {
        const int n0 = (blk & 63) * 64;
        int4* sB4 = (int4*)smem;
        for (int i = tid; i < 64 * 64; i += NTHR) {
            int r = i >> 6, q = i & 63;
            sB4[r * 65 + q] = g_wx4[(n0 + r) * 64 + q];
        }
        const int wm = wid & 3, wn = wid >> 2;
        const int l15 = lane & 15;
        const unsigned koffA = (unsigned)((lane >> 4) << 4);
        const unsigned bko   = (unsigned)(((lane >> 3) & 1) << 4);
        const int bn = (lane & 7) + ((lane >> 4) << 3);
        const int rowA = wm * 16 + l15;
        const unsigned wb0 = sb + (unsigned)((wn * 16 + bn) * 1040) + bko;

        prefetch_a(sb, tid, (blk >> 6) * 64, 0, 0);
        cpa_commit();
        for (int s = 0; s < 256; s++) {
            const int m0 = ((blk >> 6) + 2 * s) * 64;
            float acc[2][4] = {};
#pragma unroll 1
            for (int kc = 0; kc < 8; kc++) {
                cpa_wait0();
                __syncthreads();
                if (kc < 7)       { prefetch_a(sb, tid, m0, kc + 1, (kc + 1) & 1); cpa_commit(); }
                else if (s < 255) { prefetch_a(sb, tid, ((blk >> 6) + 2 * (s + 1)) * 64, 0, 0); cpa_commit(); }
                unsigned ab  = sb + B_ABASE + (unsigned)((kc & 1) * B_ABUF) + (unsigned)(rowA * 144) + koffA;
                unsigned kwb = (unsigned)(kc * 128);
#pragma unroll
                for (int ks = 0; ks < 4; ks++) {
                    unsigned ah[4], bh[4];
                    ldsm4(ah, ab + ks * 32);
                    ldsm4(bh, wb0 + kwb + ks * 32);
                    mma_f16(acc[0], ah, bh[0], bh[1]);
                    mma_f16(acc[1], ah, bh[2], bh[3]);
                }
            }
#pragma unroll
            for (int nt = 0; nt < 2; nt++)
#pragma unroll
                for (int f = 0; f < 4; f++) {
                    int row = m0 + wm * 16 + gq + (f >> 1) * 8;
                    int cn  = n0 + wn * 16 + nt * 8 + 2 * tig + (f & 1);
                    g_zx[(size_t)row * G4 + cn] = acc[nt][f] + __ldg(&bk[cn]);
                }
        }
    }
    grid_bar(gen);

    // ===== Phase C: 256 recurrent steps (fp16 W resident, h streamed, 128-k chunks) =====
    {
        int4* sW4 = (int4*)smem;
        for (int i = tid; i < 32 * 128; i += NTHR) {
            int j = i >> 7, q = i & 127;
            sW4[j * 129 + q] = g_wpk4[((size_t)blk * 32 + j) * 128 + q];
        }
        const int wm = wid & 7, wn = wid >> 3;
        const int l15 = lane & 15;
        const unsigned koffA = (unsigned)((lane >> 4) << 4);
        const unsigned bko   = (unsigned)(((lane >> 3) & 1) << 4);
        const int bn = (lane & 7) + ((lane >> 4) << 3);
        const unsigned wB0 = sb + (unsigned)((wn * 16 + bn) * 2064) + bko;
        const int rowA = wm * 16 + l15;
        float* zs = (float*)(smem + C_Z);

        __half* hb0 = (__half*)g_hb4[0];
        __half* hb1 = (__half*)g_hb4[1];

        const int gb = tid >> 2;          // batch row owned in epilogue
        const int u0 = (tid & 3) << 1;    // first of 2 hidden units
        float cst[2] = {0.f, 0.f};

        for (int t = 0; t < TT; t++) {
            const int p = t & 1;
            float zxr[2][4];
#pragma unroll
            for (int uu = 0; uu < 2; uu++) {
                size_t zb = ((size_t)gb * TT + t) * G4 + (blk << 3) + u0 + uu;
#pragma unroll
                for (int g = 0; g < 4; g++) zxr[uu][g] = __ldcg(&g_zx[zb + (size_t)g * HH]);
            }
            prefetch_h(sb, tid, p, 0, 0);
            cpa_commit();
            float acc[2][4] = {};
#pragma unroll 1
            for (int kc = 0; kc < 8; kc++) {
                cpa_wait0();
                __syncthreads();
                if (kc < 7) { prefetch_h(sb, tid, p, kc + 1, (kc + 1) & 1); cpa_commit(); }
                unsigned hbuf = sb + C_H0 + (unsigned)((kc & 1) * C_HBUF) + (unsigned)(rowA * 272) + koffA;
                unsigned kwb  = (unsigned)(kc * 256);
#pragma unroll
                for (int ks = 0; ks < 8; ks++) {
                    unsigned ah[4], bh[4];
                    ldsm4(ah, hbuf + ks * 32);
                    ldsm4(bh, wB0 + kwb + ks * 32);
                    mma_f16(acc[0], ah, bh[0], bh[1]);
                    mma_f16(acc[1], ah, bh[2], bh[3]);
                }
            }
            // exchange partial z through smem (gates live in different warps)
#pragma unroll
            for (int nt = 0; nt < 2; nt++)
#pragma unroll
                for (int f = 0; f < 4; f++) {
                    int row = wm * 16 + gq + (f >> 1) * 8;
                    int col = wn * 16 + nt * 8 + 2 * tig + (f & 1);
                    zs[row * 33 + col] = acc[nt][f];
                }
            __syncthreads();
            // gate math: thread owns (batch row gb, units u0..u0+1)
#pragma unroll
            for (int uu = 0; uu < 2; uu++) {
                int u = u0 + uu;
                float zi = zs[gb * 33 + 0 * 8 + u] + zxr[uu][0];
                float zj = zs[gb * 33 + 1 * 8 + u] + zxr[uu][1];
                float zf = zs[gb * 33 + 2 * 8 + u] + zxr[uu][2];
                float zo = zs[gb * 33 + 3 * 8 + u] + zxr[uu][3];
                float cn = cst[uu] * sigmoid_fast(zf + 1.0f) + sigmoid_fast(zi) * tanh_fast(zj);
                float hn = sigmoid_fast(zo) * tanh_fast(cn);
                cst[uu] = cn;
                int hidx = gb * HH + (blk << 3) + u;
                __half hv = __float2half_rn(hn);
                if (p) hb0[hidx] = hv; else hb1[hidx] = hv;
                if (t == TT - 1) g_hT[hidx] = hn;
            }
            grid_bar(gen);
        }
    }

    // ===== Phase D: out = hT @ w + bo =====
    {
        float* sh = (float*)smem;
        const int b_ = blk;
        for (int k = tid; k < HH; k += NTHR) sh[k] = g_hT[b_ * HH + k];
        __syncthreads();
        for (int c = tid; c < CC; c += NTHR) {
            float acc = bo[c];
#pragma unroll 8
            for (int k = 0; k < HH; k++) acc = fmaf(sh[k], w[k * CC + c], acc);
            out[b_ * CC + c] = acc;
        }
    }
}

extern "C" void kernel_launch(void* const* d_in, const int* in_sizes, int n_in,
                              void* d_out, int out_size) {
    (void)in_sizes; (void)n_in; (void)out_size;
    const float* x  = (const float*)d_in[0];
    const float* Wk = (const float*)d_in[1];
    const float* bk = (const float*)d_in[2];
    const float* w  = (const float*)d_in[3];
    const float* b  = (const float*)d_in[4];
    float* out = (float*)d_out;
    cudaFuncSetAttribute(lstm_persistent, cudaFuncAttributeMaxDynamicSharedMemorySize, DYN_SMEM);
    lstm_persistent<<<NCTA, NTHR, DYN_SMEM>>>(x, Wk, bk, w, b, out);
}

// round 9
// speedup vs baseline: 2.5634x; 1.1346x over previous
#include <cuda_runtime.h>
#include <cuda_fp16.h>

#define BB   128
#define TT   256
#define DD   512
#define HH   1024
#define G4   4096
#define CC   1000
#define NCTA 128
#define NTHR 512

// dynamic smem layout (bytes)
// phase C: W slab [32 rows][2064B] = 66048, 4 H bufs (128 rows x 272B), zs
#define C_H0    66560
#define C_HBUF  34816
#define C_Z     205824      // 128*33*4 = 16896
// phase B: Wx slab [64 rows][1040B] = 66560, 4 A bufs (64 rows x 144B)
#define B_ABASE 66560
#define B_ABUF  9216
#define DYN_SMEM 222720

// ---------------- device scratch ----------------
__device__ float g_zx[(size_t)BB * TT * G4];
__device__ int4  g_x4[BB * TT * DD / 8];              // x fp16 [row][k:512]
__device__ int4  g_wx4[DD * G4 / 8];                  // Wx fp16 TRANSPOSED [n:4096][k:512]
__device__ int4  g_wpk4[(size_t)NCTA * 32 * HH / 8];  // Wh fp16 [cta][j:32][k:1024]
__device__ int4  g_hb4[2][BB * HH / 8];               // h fp16, double buffered
__device__ float g_hT[BB * HH];
__device__ unsigned g_gen;
__device__ unsigned g_cnt;

__device__ __forceinline__ float sigmoid_fast(float x) {
    return __fdividef(1.0f, 1.0f + __expf(-x));
}
__device__ __forceinline__ float tanh_fast(float x) {
    float xc = fminf(fmaxf(x, -15.0f), 15.0f);
    float e = __expf(2.0f * xc);
    return __fdividef(e - 1.0f, e + 1.0f);
}

// fp16 mma
__device__ __forceinline__ void mma_f16(float* c, const unsigned* a, unsigned b0, unsigned b1) {
    asm volatile(
        "mma.sync.aligned.m16n8k16.row.col.f32.f16.f16.f32 "
        "{%0,%1,%2,%3}, {%4,%5,%6,%7}, {%8,%9}, {%0,%1,%2,%3};\n"
        : "+f"(c[0]), "+f"(c[1]), "+f"(c[2]), "+f"(c[3])
        : "r"(a[0]), "r"(a[1]), "r"(a[2]), "r"(a[3]), "r"(b0), "r"(b1));
}
__device__ __forceinline__ void ldsm4(unsigned* r, unsigned a) {
    asm volatile("ldmatrix.sync.aligned.m8n8.x4.shared.b16 {%0,%1,%2,%3}, [%4];\n"
                 : "=r"(r[0]), "=r"(r[1]), "=r"(r[2]), "=r"(r[3]) : "r"(a));
}

__device__ __forceinline__ void cpa16(unsigned s, const void* g) {
    asm volatile("cp.async.cg.shared.global [%0], [%1], 16;\n" :: "r"(s), "l"(g) : "memory");
}
__device__ __forceinline__ void cpa_commit() { asm volatile("cp.async.commit_group;\n" ::: "memory"); }
template<int N> __device__ __forceinline__ void cpa_waitN() {
    asm volatile("cp.async.wait_group %0;\n" :: "n"(N) : "memory");
}

// grid barrier: leader-only gpu fences
__device__ __forceinline__ void grid_bar(unsigned &gen) {
    __syncthreads();
    if (threadIdx.x == 0) {
        __threadfence();
        if (atomicAdd(&g_cnt, 1u) == NCTA - 1u) {
            g_cnt = 0u;
            __threadfence();
            atomicExch(&g_gen, gen + 1u);
        } else {
            volatile unsigned* vg = &g_gen;
            while (*vg == gen) __nanosleep(32);
            __threadfence();
        }
    }
    __syncthreads();
    gen++;
}

// phase C H-chunk loader: chunk = 128 k (16 int4 per row), row stride 272B
__device__ __forceinline__ void prefetch_h(unsigned sb, int tid, int p, int kc, int buf) {
    unsigned dst = sb + C_H0 + (unsigned)(buf * C_HBUF);
    const int4* hp = g_hb4[p];
#pragma unroll
    for (int j2 = 0; j2 < 4; j2++) {
        int e = tid + j2 * 512;              // 0..2047
        int row = e >> 4, q = e & 15;
        int gi = row * 128 + kc * 16 + q;
        cpa16(dst + (unsigned)(row * 272 + q * 16), hp + gi);
    }
}

// phase B A-chunk loader: 64 rows x 8 int4, row stride 144B
__device__ __forceinline__ void prefetch_a(unsigned sb, int tid, int m0, int kc, int buf) {
    unsigned dst = sb + B_ABASE + (unsigned)(buf * B_ABUF);
    int row = tid >> 3, q = tid & 7;
    int gi = (m0 + row) * 64 + kc * 8 + q;
    cpa16(dst + (unsigned)(row * 144 + q * 16), g_x4 + gi);
}

extern __shared__ __align__(16) unsigned char smem[];

__global__ void __launch_bounds__(NTHR, 1)
lstm_persistent(const float* __restrict__ x, const float* __restrict__ Wk,
                const float* __restrict__ bk, const float* __restrict__ w,
                const float* __restrict__ bo, float* __restrict__ out) {
    const int tid  = threadIdx.x;
    const int blk  = blockIdx.x;
    const int wid  = tid >> 5;
    const int lane = tid & 31;
    const int gq   = lane >> 2;
    const int tig  = lane & 3;
    const unsigned sb = (unsigned)__cvta_generic_to_shared(smem);

    unsigned gen = atomicAdd(&g_gen, 0u);

    const int gtid = blk * NTHR + tid;
    const int gstr = NCTA * NTHR;

    // ===== Phase A: fp16 conversions + repacks =====
    {
        const float4* x4 = (const float4*)x;
        ushort4* xo = (ushort4*)g_x4;
        for (int i = gtid; i < BB * TT * DD / 4; i += gstr) {
            float4 v = x4[i];
            ushort4 h;
            h.x = __half_as_ushort(__float2half_rn(v.x));
            h.y = __half_as_ushort(__float2half_rn(v.y));
            h.z = __half_as_ushort(__float2half_rn(v.z));
            h.w = __half_as_ushort(__float2half_rn(v.w));
            xo[i] = h;
        }
        unsigned short* wt = (unsigned short*)g_wx4;
        for (int i = gtid; i < G4 * DD; i += gstr) {
            int n = i >> 9, k = i & 511;
            wt[i] = __half_as_ushort(__float2half_rn(Wk[(size_t)k * G4 + n]));
        }
        unsigned short* wpk = (unsigned short*)g_wpk4;
        for (int i = gtid; i < NCTA * 32 * HH; i += gstr) {
            int k  = i & (HH - 1);
            int j  = (i >> 10) & 31;
            int bq = i >> 15;
            int col = ((j >> 3) << 10) + (bq << 3) + (j & 7);
            wpk[i] = __half_as_ushort(__float2half_rn(Wk[(size_t)(DD + k) * G4 + col]));
        }
        int4 z4 = make_int4(0, 0, 0, 0);
        for (int i = gtid; i < BB * HH / 8; i += gstr) {
            g_hb4[0][i] = z4; g_hb4[1][i] = z4;
        }
    }
    grid_bar(gen);

    // ===== Phase B: Zx = x @ Wx + bk  (fp16, 4-buf/3-ahead ring) =====
    {
        const int n0 = (blk & 63) * 64;
        int4* sB4 = (int4*)smem;
        for (int i = tid; i < 64 * 64; i += NTHR) {
            int r = i >> 6, q = i & 63;
            sB4[r * 65 + q] = g_wx4[(n0 + r) * 64 + q];
        }
        const int wm = wid & 3, wn = wid >> 2;
        const int l15 = lane & 15;
        const unsigned koffA = (unsigned)((lane >> 4) << 4);
        const unsigned bko   = (unsigned)(((lane >> 3) & 1) << 4);
        const int bn = (lane & 7) + ((lane >> 4) << 3);
        const int rowA = wm * 16 + l15;
        const unsigned wb0 = sb + (unsigned)((wn * 16 + bn) * 1040) + bko;

        // prologue: chunks 0,1,2 of tile 0
        const int m00 = (blk >> 6) * 64;
        prefetch_a(sb, tid, m00, 0, 0); cpa_commit();
        prefetch_a(sb, tid, m00, 1, 1); cpa_commit();
        prefetch_a(sb, tid, m00, 2, 2); cpa_commit();

        for (int s = 0; s < 256; s++) {
            const int m0 = ((blk >> 6) + 2 * s) * 64;
            float acc[2][4] = {};
#pragma unroll 1
            for (int kc = 0; kc < 8; kc++) {
                int gkc = s * 8 + kc;
                if (gkc + 3 < 2048) {
                    cpa_waitN<2>();
                    __syncthreads();
                    int g2 = gkc + 3, s2 = g2 >> 3, kc2 = g2 & 7;
                    prefetch_a(sb, tid, ((blk >> 6) + 2 * s2) * 64, kc2, g2 & 3);
                    cpa_commit();
                } else {
                    int rem = 2047 - gkc;
                    if (rem >= 2)      cpa_waitN<2>();
                    else if (rem == 1) cpa_waitN<1>();
                    else               cpa_waitN<0>();
                    __syncthreads();
                }
                unsigned ab  = sb + B_ABASE + (unsigned)((gkc & 3) * B_ABUF)
                             + (unsigned)(rowA * 144) + koffA;
                unsigned kwb = (unsigned)(kc * 128);
#pragma unroll
                for (int ks = 0; ks < 4; ks++) {
                    unsigned ah[4], bh[4];
                    ldsm4(ah, ab + ks * 32);
                    ldsm4(bh, wb0 + kwb + ks * 32);
                    mma_f16(acc[0], ah, bh[0], bh[1]);
                    mma_f16(acc[1], ah, bh[2], bh[3]);
                }
            }
#pragma unroll
            for (int nt = 0; nt < 2; nt++)
#pragma unroll
                for (int f = 0; f < 4; f++) {
                    int row = m0 + wm * 16 + gq + (f >> 1) * 8;
                    int cn  = n0 + wn * 16 + nt * 8 + 2 * tig + (f & 1);
                    g_zx[(size_t)row * G4 + cn] = acc[nt][f] + __ldg(&bk[cn]);
                }
        }
    }
    grid_bar(gen);

    // ===== Phase C: 256 recurrent steps (W resident, h streamed, 4-buf ring) =====
    {
        int4* sW4 = (int4*)smem;
        for (int i = tid; i < 32 * 128; i += NTHR) {
            int j = i >> 7, q = i & 127;
            sW4[j * 129 + q] = g_wpk4[((size_t)blk * 32 + j) * 128 + q];
        }
        const int wm = wid & 7, wn = wid >> 3;
        const int l15 = lane & 15;
        const unsigned koffA = (unsigned)((lane >> 4) << 4);
        const unsigned bko   = (unsigned)(((lane >> 3) & 1) << 4);
        const int bn = (lane & 7) + ((lane >> 4) << 3);
        const unsigned wB0 = sb + (unsigned)((wn * 16 + bn) * 2064) + bko;
        const int rowA = wm * 16 + l15;
        float* zs = (float*)(smem + C_Z);

        __half2* hb2[2] = { (__half2*)g_hb4[0], (__half2*)g_hb4[1] };

        const int gb = tid >> 2;          // batch row owned in epilogue
        const int u0 = (tid & 3) << 1;    // first of 2 hidden units (even)
        float cst[2] = {0.f, 0.f};

        __syncthreads();

        float acc[2][4];
        float zxr[2][4];
        // zxr for t=0
#pragma unroll
        for (int uu = 0; uu < 2; uu++) {
            size_t zb = ((size_t)gb * TT + 0) * G4 + (blk << 3) + u0 + uu;
#pragma unroll
            for (int g = 0; g < 4; g++) zxr[uu][g] = __ldcg(&g_zx[zb + (size_t)g * HH]);
        }

        auto chunkC = [&](int kc) {
            unsigned hbuf = sb + C_H0 + (unsigned)((kc & 3) * C_HBUF)
                          + (unsigned)(rowA * 272) + koffA;
            unsigned kwb  = (unsigned)(kc * 256);
#pragma unroll
            for (int ks = 0; ks < 8; ks++) {
                unsigned ah[4], bh[4];
                ldsm4(ah, hbuf + ks * 32);
                ldsm4(bh, wB0 + kwb + ks * 32);
                mma_f16(acc[0], ah, bh[0], bh[1]);
                mma_f16(acc[1], ah, bh[2], bh[3]);
            }
        };

        for (int t = 0; t < TT; t++) {
            const int p = t & 1;
            // prologue: 3 chunks ahead
            prefetch_h(sb, tid, p, 0, 0); cpa_commit();
            prefetch_h(sb, tid, p, 1, 1); cpa_commit();
            prefetch_h(sb, tid, p, 2, 2); cpa_commit();
#pragma unroll
            for (int nt = 0; nt < 2; nt++)
#pragma unroll
                for (int f = 0; f < 4; f++) acc[nt][f] = 0.f;

#pragma unroll 1
            for (int kc = 0; kc < 5; kc++) {
                cpa_waitN<2>();
                __syncthreads();
                prefetch_h(sb, tid, p, kc + 3, (kc + 3) & 3);
                cpa_commit();
                chunkC(kc);
            }
            cpa_waitN<2>(); __syncthreads(); chunkC(5);
            cpa_waitN<1>(); __syncthreads(); chunkC(6);
            cpa_waitN<0>(); __syncthreads(); chunkC(7);

            // exchange partial z through smem (gates live in different warps)
#pragma unroll
            for (int nt = 0; nt < 2; nt++)
#pragma unroll
                for (int f = 0; f < 4; f++) {
                    int row = wm * 16 + gq + (f >> 1) * 8;
                    int col = wn * 16 + nt * 8 + 2 * tig + (f & 1);
                    zs[row * 33 + col] = acc[nt][f];
                }
            __syncthreads();
            // gate math: thread owns (batch row gb, units u0..u0+1)
            float hnv[2];
#pragma unroll
            for (int uu = 0; uu < 2; uu++) {
                int u = u0 + uu;
                float zi = zs[gb * 33 + 0 * 8 + u] + zxr[uu][0];
                float zj = zs[gb * 33 + 1 * 8 + u] + zxr[uu][1];
                float zf = zs[gb * 33 + 2 * 8 + u] + zxr[uu][2];
                float zo = zs[gb * 33 + 3 * 8 + u] + zxr[uu][3];
                float cn = cst[uu] * sigmoid_fast(zf + 1.0f) + sigmoid_fast(zi) * tanh_fast(zj);
                hnv[uu] = sigmoid_fast(zo) * tanh_fast(cn);
                cst[uu] = cn;
            }
            {
                __half2 hv = __halves2half2(__float2half_rn(hnv[0]), __float2half_rn(hnv[1]));
                hb2[1 - p][(gb * HH + (blk << 3) + u0) >> 1] = hv;
            }
            if (t == TT - 1) {
                g_hT[gb * HH + (blk << 3) + u0]     = hnv[0];
                g_hT[gb * HH + (blk << 3) + u0 + 1] = hnv[1];
            } else {
                // prefetch zx for t+1 before the barrier (overlaps spin)
#pragma unroll
                for (int uu = 0; uu < 2; uu++) {
                    size_t zb = ((size_t)gb * TT + (t + 1)) * G4 + (blk << 3) + u0 + uu;
#pragma unroll
                    for (int g = 0; g < 4; g++) zxr[uu][g] = __ldcg(&g_zx[zb + (size_t)g * HH]);
                }
            }
            grid_bar(gen);
        }
    }

    // ===== Phase D: out = hT @ w + bo =====
    {
        float* sh = (float*)smem;
        const int b_ = blk;
        for (int k = tid; k < HH; k += NTHR) sh[k] = g_hT[b_ * HH + k];
        __syncthreads();
        for (int c = tid; c < CC; c += NTHR) {
            float acc = bo[c];
#pragma unroll 8
            for (int k = 0; k < HH; k++) acc = fmaf(sh[k], w[k * CC + c], acc);
            out[b_ * CC + c] = acc;
        }
    }
}

extern "C" void kernel_launch(void* const* d_in, const int* in_sizes, int n_in,
                              void* d_out, int out_size) {
    (void)in_sizes; (void)n_in; (void)out_size;
    const float* x  = (const float*)d_in[0];
    const float* Wk = (const float*)d_in[1];
    const float* bk = (const float*)d_in[2];
    const float* w  = (const float*)d_in[3];
    const float* b  = (const float*)d_in[4];
    float* out = (float*)d_out;
    cudaFuncSetAttribute(lstm_persistent, cudaFuncAttributeMaxDynamicSharedMemorySize, DYN_SMEM);
    lstm_persistent<<<NCTA, NTHR, DYN_SMEM>>>(x, Wk, bk, w, b, out);
}

// round 10
// speedup vs baseline: 3.0155x; 1.1764x over previous
#include <cuda_runtime.h>
#include <cuda_fp16.h>

#define BB   128
#define TT   256
#define DD   512
#define HH   1024
#define G4   4096
#define CC   1000
#define NCTA 128
#define NTHR 512

// dynamic smem layout (bytes)
// phase C: W slab [32 rows][2064B] = 66048, zs 2 slabs of 16896
#define C_Z     66048
#define C_ZSLAB 16896
// phase B: Wx slab [64 rows][1040B] = 66560, 4 A bufs (64 rows x 144B)
#define B_ABASE 66560
#define B_ABUF  9216
#define DYN_SMEM 103424

// ---------------- device scratch ----------------
__device__ float g_zx[(size_t)BB * TT * G4];
__device__ int4  g_x4[BB * TT * DD / 8];              // x fp16 [row][k:512]
__device__ int4  g_wx4[DD * G4 / 8];                  // Wx fp16 TRANSPOSED [n:4096][k:512]
__device__ int4  g_wpk4[(size_t)NCTA * 32 * HH / 8];  // Wh fp16 [cta][j:32][k:1024]
// h double buffered, FRAGMENT-MAJOR layout:
// tile (rg = row>>4, kt = k>>4) is a 512B block at (rg*64+kt)*512;
// lane L = gq*4+tig holds int4 at +L*16 = { (gq,2t..+1), (gq+8,2t..+1), (gq,8+2t..), (gq+8,8+2t..) }
__device__ int4  g_hb4[2][BB * HH / 8];
__device__ float g_hT[BB * HH];
__device__ unsigned g_gen;
__device__ unsigned g_cnt;

__device__ __forceinline__ float sigmoid_fast(float x) {
    return __fdividef(1.0f, 1.0f + __expf(-x));
}
__device__ __forceinline__ float tanh_fast(float x) {
    float xc = fminf(fmaxf(x, -15.0f), 15.0f);
    float e = __expf(2.0f * xc);
    return __fdividef(e - 1.0f, e + 1.0f);
}

// fp16 mma
__device__ __forceinline__ void mma_f16(float* c, const unsigned* a, unsigned b0, unsigned b1) {
    asm volatile(
        "mma.sync.aligned.m16n8k16.row.col.f32.f16.f16.f32 "
        "{%0,%1,%2,%3}, {%4,%5,%6,%7}, {%8,%9}, {%0,%1,%2,%3};\n"
        : "+f"(c[0]), "+f"(c[1]), "+f"(c[2]), "+f"(c[3])
        : "r"(a[0]), "r"(a[1]), "r"(a[2]), "r"(a[3]), "r"(b0), "r"(b1));
}
__device__ __forceinline__ void ldsm4(unsigned* r, unsigned a) {
    asm volatile("ldmatrix.sync.aligned.m8n8.x4.shared.b16 {%0,%1,%2,%3}, [%4];\n"
                 : "=r"(r[0]), "=r"(r[1]), "=r"(r[2]), "=r"(r[3]) : "r"(a));
}

__device__ __forceinline__ void cpa16(unsigned s, const void* g) {
    asm volatile("cp.async.cg.shared.global [%0], [%1], 16;\n" :: "r"(s), "l"(g) : "memory");
}
__device__ __forceinline__ void cpa_commit() { asm volatile("cp.async.commit_group;\n" ::: "memory"); }
template<int N> __device__ __forceinline__ void cpa_waitN() {
    asm volatile("cp.async.wait_group %0;\n" :: "n"(N) : "memory");
}

// grid barrier: leader-only gpu fences, tight spin
__device__ __forceinline__ void grid_bar(unsigned &gen) {
    __syncthreads();
    if (threadIdx.x == 0) {
        __threadfence();
        if (atomicAdd(&g_cnt, 1u) == NCTA - 1u) {
            g_cnt = 0u;
            __threadfence();
            atomicExch(&g_gen, gen + 1u);
        } else {
            volatile unsigned* vg = &g_gen;
            while (*vg == gen) {}
            __threadfence();
        }
    }
    __syncthreads();
    gen++;
}

// phase B A-chunk loader: 64 rows x 8 int4, row stride 144B
__device__ __forceinline__ void prefetch_a(unsigned sb, int tid, int m0, int kc, int buf) {
    unsigned dst = sb + B_ABASE + (unsigned)(buf * B_ABUF);
    int row = tid >> 3, q = tid & 7;
    int gi = (m0 + row) * 64 + kc * 8 + q;
    cpa16(dst + (unsigned)(row * 144 + q * 16), g_x4 + gi);
}

extern __shared__ __align__(16) unsigned char smem[];

__global__ void __launch_bounds__(NTHR, 1)
lstm_persistent(const float* __restrict__ x, const float* __restrict__ Wk,
                const float* __restrict__ bk, const float* __restrict__ w,
                const float* __restrict__ bo, float* __restrict__ out) {
    const int tid  = threadIdx.x;
    const int blk  = blockIdx.x;
    const int wid  = tid >> 5;
    const int lane = tid & 31;
    const int gq   = lane >> 2;
    const int tig  = lane & 3;
    const unsigned sb = (unsigned)__cvta_generic_to_shared(smem);

    unsigned gen = atomicAdd(&g_gen, 0u);

    const int gtid = blk * NTHR + tid;
    const int gstr = NCTA * NTHR;

    // ===== Phase A: fp16 conversions + repacks =====
    {
        const float4* x4 = (const float4*)x;
        ushort4* xo = (ushort4*)g_x4;
        for (int i = gtid; i < BB * TT * DD / 4; i += gstr) {
            float4 v = x4[i];
            ushort4 h;
            h.x = __half_as_ushort(__float2half_rn(v.x));
            h.y = __half_as_ushort(__float2half_rn(v.y));
            h.z = __half_as_ushort(__float2half_rn(v.z));
            h.w = __half_as_ushort(__float2half_rn(v.w));
            xo[i] = h;
        }
        unsigned short* wt = (unsigned short*)g_wx4;
        for (int i = gtid; i < G4 * DD; i += gstr) {
            int n = i >> 9, k = i & 511;
            wt[i] = __half_as_ushort(__float2half_rn(Wk[(size_t)k * G4 + n]));
        }
        unsigned short* wpk = (unsigned short*)g_wpk4;
        for (int i = gtid; i < NCTA * 32 * HH; i += gstr) {
            int k  = i & (HH - 1);
            int j  = (i >> 10) & 31;
            int bq = i >> 15;
            int col = ((j >> 3) << 10) + (bq << 3) + (j & 7);
            wpk[i] = __half_as_ushort(__float2half_rn(Wk[(size_t)(DD + k) * G4 + col]));
        }
        int4 z4 = make_int4(0, 0, 0, 0);
        for (int i = gtid; i < BB * HH / 8; i += gstr) {
            g_hb4[0][i] = z4; g_hb4[1][i] = z4;
        }
    }
    grid_bar(gen);

    // ===== Phase B: Zx = x @ Wx + bk  (fp16, 4-buf/3-ahead ring) =====
    {
        const int n0 = (blk & 63) * 64;
        int4* sB4 = (int4*)smem;
        for (int i = tid; i < 64 * 64; i += NTHR) {
            int r = i >> 6, q = i & 63;
            sB4[r * 65 + q] = g_wx4[(n0 + r) * 64 + q];
        }
        const int wm = wid & 3, wn = wid >> 2;
        const int l15 = lane & 15;
        const unsigned koffA = (unsigned)((lane >> 4) << 4);
        const unsigned bko   = (unsigned)(((lane >> 3) & 1) << 4);
        const int bn = (lane & 7) + ((lane >> 4) << 3);
        const int rowA = wm * 16 + l15;
        const unsigned wb0 = sb + (unsigned)((wn * 16 + bn) * 1040) + bko;

        const int m00 = (blk >> 6) * 64;
        prefetch_a(sb, tid, m00, 0, 0); cpa_commit();
        prefetch_a(sb, tid, m00, 1, 1); cpa_commit();
        prefetch_a(sb, tid, m00, 2, 2); cpa_commit();

        for (int s = 0; s < 256; s++) {
            const int m0 = ((blk >> 6) + 2 * s) * 64;
            float acc[2][4] = {};
#pragma unroll 1
            for (int kc = 0; kc < 8; kc++) {
                int gkc = s * 8 + kc;
                if (gkc + 3 < 2048) {
                    cpa_waitN<2>();
                    __syncthreads();
                    int g2 = gkc + 3, s2 = g2 >> 3, kc2 = g2 & 7;
                    prefetch_a(sb, tid, ((blk >> 6) + 2 * s2) * 64, kc2, g2 & 3);
                    cpa_commit();
                } else {
                    int rem = 2047 - gkc;
                    if (rem >= 2)      cpa_waitN<2>();
                    else if (rem == 1) cpa_waitN<1>();
                    else               cpa_waitN<0>();
                    __syncthreads();
                }
                unsigned ab  = sb + B_ABASE + (unsigned)((gkc & 3) * B_ABUF)
                             + (unsigned)(rowA * 144) + koffA;
                unsigned kwb = (unsigned)(kc * 128);
#pragma unroll
                for (int ks = 0; ks < 4; ks++) {
                    unsigned ah[4], bh[4];
                    ldsm4(ah, ab + ks * 32);
                    ldsm4(bh, wb0 + kwb + ks * 32);
                    mma_f16(acc[0], ah, bh[0], bh[1]);
                    mma_f16(acc[1], ah, bh[2], bh[3]);
                }
            }
#pragma unroll
            for (int nt = 0; nt < 2; nt++)
#pragma unroll
                for (int f = 0; f < 4; f++) {
                    int row = m0 + wm * 16 + gq + (f >> 1) * 8;
                    int cn  = n0 + wn * 16 + nt * 8 + 2 * tig + (f & 1);
                    g_zx[(size_t)row * G4 + cn] = acc[nt][f] + __ldg(&bk[cn]);
                }
        }
    }
    grid_bar(gen);

    // ===== Phase C: 256 steps. W smem-resident; h fragments LDG'd direct from L2 =====
    {
        int4* sW4 = (int4*)smem;
        for (int i = tid; i < 32 * 128; i += NTHR) {
            int j = i >> 7, q = i & 127;
            sW4[j * 129 + q] = g_wpk4[((size_t)blk * 32 + j) * 128 + q];
        }
        __syncthreads();

        const int wm  = wid & 3;    // 4 row groups of 32
        const int ksg = wid >> 2;   // 4 k groups of 256
        const unsigned bko = (unsigned)(((lane >> 3) & 1) << 4);
        const int bn = (lane & 7) + ((lane >> 4) << 3);
        const unsigned wB0 = sb + (unsigned)(bn * 2064) + bko + (unsigned)(ksg * 512);
        const unsigned wB1 = wB0 + 16u * 2064u;
        float* zs0 = (float*)(smem + C_Z);
        float* zs1 = (float*)(smem + C_Z + C_ZSLAB);
        float* zsw = (ksg & 1) ? zs1 : zs0;

        const int gb = tid >> 2;          // batch row owned in epilogue
        const int u0 = (tid & 3) << 1;    // first of 2 hidden units (even)
        float cst[2] = {0.f, 0.f};

        // writer address for h (fragment-major): k = blk*8 + u0 (+1 in same word)
        const int kw  = blk * 8 + u0;
        const int w_tile = ((gb >> 4) * 64 + (kw >> 4));
        const int w_word = ((gb & 7) * 4 + (((kw & 7)) >> 1)) * 4 + (((kw & 15) >> 3) * 2 + ((gb >> 3) & 1));
        const int w_idx = w_tile * 128 + w_word;   // index in half2 units (tile = 512B = 128 half2)

        float zxr[2][4];
#pragma unroll
        for (int uu = 0; uu < 2; uu++) {
            size_t zb = ((size_t)gb * TT + 0) * G4 + (blk << 3) + u0 + uu;
#pragma unroll
            for (int g = 0; g < 4; g++) zxr[uu][g] = __ldcg(&g_zx[zb + (size_t)g * HH]);
        }

        for (int t = 0; t < TT; t++) {
            const int p = t & 1;
            const int4* hp = g_hb4[p];
            float acc[8][4];
#pragma unroll
            for (int i = 0; i < 8; i++)
#pragma unroll
                for (int f = 0; f < 4; f++) acc[i][f] = 0.f;

#pragma unroll 4
            for (int ks = 0; ks < 16; ks++) {
                int kt = ksg * 16 + ks;
                int4 av0 = __ldcg(hp + ((wm * 2 + 0) * 64 + kt) * 32 + lane);
                int4 av1 = __ldcg(hp + ((wm * 2 + 1) * 64 + kt) * 32 + lane);
                unsigned b0[4], b1[4];
                ldsm4(b0, wB0 + ks * 32);
                ldsm4(b1, wB1 + ks * 32);
                unsigned a0[4] = {(unsigned)av0.x, (unsigned)av0.y, (unsigned)av0.z, (unsigned)av0.w};
                unsigned a1[4] = {(unsigned)av1.x, (unsigned)av1.y, (unsigned)av1.z, (unsigned)av1.w};
                mma_f16(acc[0], a0, b0[0], b0[1]);
                mma_f16(acc[1], a0, b0[2], b0[3]);
                mma_f16(acc[2], a0, b1[0], b1[1]);
                mma_f16(acc[3], a0, b1[2], b1[3]);
                mma_f16(acc[4], a1, b0[0], b0[1]);
                mma_f16(acc[5], a1, b0[2], b0[3]);
                mma_f16(acc[6], a1, b1[0], b1[1]);
                mma_f16(acc[7], a1, b1[2], b1[3]);
            }

            // k-split reduction through 2 zs slabs
            if (ksg < 2) {
#pragma unroll
                for (int mt = 0; mt < 2; mt++)
#pragma unroll
                    for (int ci = 0; ci < 4; ci++)
#pragma unroll
                        for (int f = 0; f < 4; f++) {
                            int row = wm * 32 + mt * 16 + gq + (f >> 1) * 8;
                            int col = ci * 8 + 2 * tig + (f & 1);
                            zsw[row * 33 + col] = acc[mt * 4 + ci][f];
                        }
            }
            __syncthreads();
            if (ksg >= 2) {
#pragma unroll
                for (int mt = 0; mt < 2; mt++)
#pragma unroll
                    for (int ci = 0; ci < 4; ci++)
#pragma unroll
                        for (int f = 0; f < 4; f++) {
                            int row = wm * 32 + mt * 16 + gq + (f >> 1) * 8;
                            int col = ci * 8 + 2 * tig + (f & 1);
                            zsw[row * 33 + col] += acc[mt * 4 + ci][f];
                        }
            }
            __syncthreads();

            // gate math: thread owns (batch row gb, units u0..u0+1)
            float hnv[2];
#pragma unroll
            for (int uu = 0; uu < 2; uu++) {
                int u = u0 + uu;
                float zi = zs0[gb * 33 + 0 * 8 + u] + zs1[gb * 33 + 0 * 8 + u] + zxr[uu][0];
                float zj = zs0[gb * 33 + 1 * 8 + u] + zs1[gb * 33 + 1 * 8 + u] + zxr[uu][1];
                float zf = zs0[gb * 33 + 2 * 8 + u] + zs1[gb * 33 + 2 * 8 + u] + zxr[uu][2];
                float zo = zs0[gb * 33 + 3 * 8 + u] + zs1[gb * 33 + 3 * 8 + u] + zxr[uu][3];
                float cn = cst[uu] * sigmoid_fast(zf + 1.0f) + sigmoid_fast(zi) * tanh_fast(zj);
                hnv[uu] = sigmoid_fast(zo) * tanh_fast(cn);
                cst[uu] = cn;
            }
            {
                __half2 hv = __halves2half2(__float2half_rn(hnv[0]), __float2half_rn(hnv[1]));
                ((__half2*)g_hb4[1 - p])[w_idx] = hv;
            }
            if (t == TT - 1) {
                g_hT[gb * HH + (blk << 3) + u0]     = hnv[0];
                g_hT[gb * HH + (blk << 3) + u0 + 1] = hnv[1];
            } else {
#pragma unroll
                for (int uu = 0; uu < 2; uu++) {
                    size_t zb = ((size_t)gb * TT + (t + 1)) * G4 + (blk << 3) + u0 + uu;
#pragma unroll
                    for (int g = 0; g < 4; g++) zxr[uu][g] = __ldcg(&g_zx[zb + (size_t)g * HH]);
                }
            }
            grid_bar(gen);
        }
    }

    // ===== Phase D: out = hT @ w + bo =====
    {
        float* sh = (float*)smem;
        const int b_ = blk;
        for (int k = tid; k < HH; k += NTHR) sh[k] = g_hT[b_ * HH + k];
        __syncthreads();
        for (int c = tid; c < CC; c += NTHR) {
            float acc = bo[c];
#pragma unroll 8
            for (int k = 0; k < HH; k++) acc = fmaf(sh[k], w[k * CC + c], acc);
            out[b_ * CC + c] = acc;
        }
    }
}

extern "C" void kernel_launch(void* const* d_in, const int* in_sizes, int n_in,
                              void* d_out, int out_size) {
    (void)in_sizes; (void)n_in; (void)out_size;
    const float* x  = (const float*)d_in[0];
    const float* Wk = (const float*)d_in[1];
    const float* bk = (const float*)d_in[2];
    const float* w  = (const float*)d_in[3];
    const float* b  = (const float*)d_in[4];
    float* out = (float*)d_out;
    cudaFuncSetAttribute(lstm_persistent, cudaFuncAttributeMaxDynamicSharedMemorySize, DYN_SMEM);
    lstm_persistent<<<NCTA, NTHR, DYN_SMEM>>>(x, Wk, bk, w, b, out);
}

// round 11
// speedup vs baseline: 3.1743x; 1.0527x over previous
#include <cuda_runtime.h>
#include <cuda_fp16.h>

#define BB   128
#define TT   256
#define DD   512
#define HH   1024
#define G4   4096
#define CC   1000
#define NCTA 128
#define NTHR 512

// dynamic smem layout (bytes)
// phase C: W slab [32 rows][2064B] = 66048, zs 2 slabs of 16896
#define C_Z     66048
#define C_ZSLAB 16896
// phase B: Wx slab [64 rows][1040B] = 66560 (no A bufs anymore)
#define DYN_SMEM 99840

// ---------------- device scratch ----------------
__device__ float g_zx[(size_t)BB * TT * G4];
// x in MMA-fragment-major layout: tile (rt = row>>4, kt = k>>4) is a 512B block
// at (rt*32+kt)*512; lane L = gq*4+tig holds int4 = its 4 A-registers.
__device__ int4  g_xf[BB * TT * DD / 8];
__device__ int4  g_wx4[DD * G4 / 8];                  // Wx fp16 TRANSPOSED [n:4096][k:512]
__device__ int4  g_wpk4[(size_t)NCTA * 32 * HH / 8];  // Wh fp16 [cta][j:32][k:1024]
// h double buffered, fragment-major (same tile convention, 64 k-tiles per row-tile)
__device__ int4  g_hb4[2][BB * HH / 8];
__device__ float g_hT[BB * HH];
__device__ unsigned g_gen;
__device__ unsigned g_cnt;

__device__ __forceinline__ float sigmoid_fast(float x) {
    return __fdividef(1.0f, 1.0f + __expf(-x));
}
__device__ __forceinline__ float tanh_fast(float x) {
    float xc = fminf(fmaxf(x, -15.0f), 15.0f);
    float e = __expf(2.0f * xc);
    return __fdividef(e - 1.0f, e + 1.0f);
}

// fp16 mma
__device__ __forceinline__ void mma_f16(float* c, const unsigned* a, unsigned b0, unsigned b1) {
    asm volatile(
        "mma.sync.aligned.m16n8k16.row.col.f32.f16.f16.f32 "
        "{%0,%1,%2,%3}, {%4,%5,%6,%7}, {%8,%9}, {%0,%1,%2,%3};\n"
        : "+f"(c[0]), "+f"(c[1]), "+f"(c[2]), "+f"(c[3])
        : "r"(a[0]), "r"(a[1]), "r"(a[2]), "r"(a[3]), "r"(b0), "r"(b1));
}
__device__ __forceinline__ void ldsm4(unsigned* r, unsigned a) {
    asm volatile("ldmatrix.sync.aligned.m8n8.x4.shared.b16 {%0,%1,%2,%3}, [%4];\n"
                 : "=r"(r[0]), "=r"(r[1]), "=r"(r[2]), "=r"(r[3]) : "r"(a));
}

// grid barrier: leader-only gpu fences, tight spin
__device__ __forceinline__ void grid_bar(unsigned &gen) {
    __syncthreads();
    if (threadIdx.x == 0) {
        __threadfence();
        if (atomicAdd(&g_cnt, 1u) == NCTA - 1u) {
            g_cnt = 0u;
            __threadfence();
            atomicExch(&g_gen, gen + 1u);
        } else {
            volatile unsigned* vg = &g_gen;
            while (*vg == gen) {}
            __threadfence();
        }
    }
    __syncthreads();
    gen++;
}

__device__ __forceinline__ unsigned packh2(float lo, float hi) {
    __half2 h = __floats2half2_rn(lo, hi);
    return *(unsigned*)&h;
}

extern __shared__ __align__(16) unsigned char smem[];

__global__ void __launch_bounds__(NTHR, 1)
lstm_persistent(const float* __restrict__ x, const float* __restrict__ Wk,
                const float* __restrict__ bk, const float* __restrict__ w,
                const float* __restrict__ bo, float* __restrict__ out) {
    const int tid  = threadIdx.x;
    const int blk  = blockIdx.x;
    const int wid  = tid >> 5;
    const int lane = tid & 31;
    const int gq   = lane >> 2;
    const int tig  = lane & 3;
    const unsigned sb = (unsigned)__cvta_generic_to_shared(smem);

    unsigned gen = atomicAdd(&g_gen, 0u);

    const int gtid = blk * NTHR + tid;
    const int gstr = NCTA * NTHR;

    // ===== Phase A: fp16 conversions + repacks =====
    {
        // x -> fragment-major fp16 (2048 row-tiles x 32 k-tiles x 32 lanes)
        for (int i = gtid; i < 2048 * 32 * 32; i += gstr) {
            int ln = i & 31, kt = (i >> 5) & 31, rt = i >> 10;
            int gq_ = ln >> 2, tg = ln & 3;
            const float* xr0 = x + (size_t)(rt * 16 + gq_) * DD + kt * 16;
            const float* xr1 = xr0 + 8 * DD;
            float2 v0 = *(const float2*)(xr0 + 2 * tg);
            float2 v1 = *(const float2*)(xr1 + 2 * tg);
            float2 v2 = *(const float2*)(xr0 + 8 + 2 * tg);
            float2 v3 = *(const float2*)(xr1 + 8 + 2 * tg);
            int4 o;
            o.x = (int)packh2(v0.x, v0.y);
            o.y = (int)packh2(v1.x, v1.y);
            o.z = (int)packh2(v2.x, v2.y);
            o.w = (int)packh2(v3.x, v3.y);
            g_xf[i] = o;
        }
        unsigned short* wt = (unsigned short*)g_wx4;
        for (int i = gtid; i < G4 * DD; i += gstr) {
            int n = i >> 9, k = i & 511;
            wt[i] = __half_as_ushort(__float2half_rn(Wk[(size_t)k * G4 + n]));
        }
        unsigned short* wpk = (unsigned short*)g_wpk4;
        for (int i = gtid; i < NCTA * 32 * HH; i += gstr) {
            int k  = i & (HH - 1);
            int j  = (i >> 10) & 31;
            int bq = i >> 15;
            int col = ((j >> 3) << 10) + (bq << 3) + (j & 7);
            wpk[i] = __half_as_ushort(__float2half_rn(Wk[(size_t)(DD + k) * G4 + col]));
        }
        int4 z4 = make_int4(0, 0, 0, 0);
        for (int i = gtid; i < BB * HH / 8; i += gstr) {
            g_hb4[0][i] = z4; g_hb4[1][i] = z4;
        }
    }
    grid_bar(gen);

    // ===== Phase B: Zx = x @ Wx + bk  (x fragments LDG'd from L2, W smem-resident) =====
    {
        const int n0 = (blk & 63) * 64;
        int4* sB4 = (int4*)smem;
        for (int i = tid; i < 64 * 64; i += NTHR) {
            int r = i >> 6, q = i & 63;
            sB4[r * 65 + q] = g_wx4[(n0 + r) * 64 + q];
        }
        __syncthreads();

        const int wm = wid & 3, wn = wid >> 2;
        const unsigned bko = (unsigned)(((lane >> 3) & 1) << 4);
        const int bn = (lane & 7) + ((lane >> 4) << 3);
        const unsigned wb0 = sb + (unsigned)((wn * 16 + bn) * 1040) + bko;

#pragma unroll 1
        for (int s = 0; s < 256; s++) {
            const int rt = ((blk >> 6) + 2 * s) * 4 + wm;   // this warp's 16-row tile
            const int4* xf = g_xf + (size_t)rt * 1024 + lane;
            float acc[2][4] = {};
#pragma unroll 8
            for (int kt = 0; kt < 32; kt++) {
                int4 av = __ldg(xf + kt * 32);
                unsigned bh[4];
                ldsm4(bh, wb0 + kt * 32);
                unsigned a[4] = {(unsigned)av.x, (unsigned)av.y, (unsigned)av.z, (unsigned)av.w};
                mma_f16(acc[0], a, bh[0], bh[1]);
                mma_f16(acc[1], a, bh[2], bh[3]);
            }
#pragma unroll
            for (int nt = 0; nt < 2; nt++)
#pragma unroll
                for (int f = 0; f < 4; f++) {
                    int row = rt * 16 + gq + (f >> 1) * 8;
                    int cn  = n0 + wn * 16 + nt * 8 + 2 * tig + (f & 1);
                    g_zx[(size_t)row * G4 + cn] = acc[nt][f] + __ldg(&bk[cn]);
                }
        }
    }
    grid_bar(gen);

    // ===== Phase C: 256 steps. W smem-resident; h fragments LDG'd direct from L2 =====
    {
        int4* sW4 = (int4*)smem;
        for (int i = tid; i < 32 * 128; i += NTHR) {
            int j = i >> 7, q = i & 127;
            sW4[j * 129 + q] = g_wpk4[((size_t)blk * 32 + j) * 128 + q];
        }
        __syncthreads();

        const int wm  = wid & 3;    // 4 row groups of 32
        const int ksg = wid >> 2;   // 4 k groups of 256
        const unsigned bko = (unsigned)(((lane >> 3) & 1) << 4);
        const int bn = (lane & 7) + ((lane >> 4) << 3);
        const unsigned wB0 = sb + (unsigned)(bn * 2064) + bko + (unsigned)(ksg * 512);
        const unsigned wB1 = wB0 + 16u * 2064u;
        float* zs0 = (float*)(smem + C_Z);
        float* zs1 = (float*)(smem + C_Z + C_ZSLAB);
        float* zsw = (ksg & 1) ? zs1 : zs0;

        const int gb = tid >> 2;          // batch row owned in epilogue
        const int u0 = (tid & 3) << 1;    // first of 2 hidden units (even)
        float cst[2] = {0.f, 0.f};

        // writer address for h (fragment-major): k = blk*8 + u0 (+1 in same word)
        const int kw  = blk * 8 + u0;
        const int w_tile = ((gb >> 4) * 64 + (kw >> 4));
        const int w_word = ((gb & 7) * 4 + (((kw & 7)) >> 1)) * 4 + (((kw & 15) >> 3) * 2 + ((gb >> 3) & 1));
        const int w_idx = w_tile * 128 + w_word;   // index in half2 units

        float zxr[2][4];
#pragma unroll
        for (int uu = 0; uu < 2; uu++) {
            size_t zb = ((size_t)gb * TT + 0) * G4 + (blk << 3) + u0 + uu;
#pragma unroll
            for (int g = 0; g < 4; g++) zxr[uu][g] = __ldcg(&g_zx[zb + (size_t)g * HH]);
        }

        for (int t = 0; t < TT; t++) {
            const int p = t & 1;
            const int4* hp = g_hb4[p];
            float acc[8][4];
#pragma unroll
            for (int i = 0; i < 8; i++)
#pragma unroll
                for (int f = 0; f < 4; f++) acc[i][f] = 0.f;

#pragma unroll 4
            for (int ks = 0; ks < 16; ks++) {
                int kt = ksg * 16 + ks;
                int4 av0 = __ldcg(hp + ((wm * 2 + 0) * 64 + kt) * 32 + lane);
                int4 av1 = __ldcg(hp + ((wm * 2 + 1) * 64 + kt) * 32 + lane);
                unsigned b0[4], b1[4];
                ldsm4(b0, wB0 + ks * 32);
                ldsm4(b1, wB1 + ks * 32);
                unsigned a0[4] = {(unsigned)av0.x, (unsigned)av0.y, (unsigned)av0.z, (unsigned)av0.w};
                unsigned a1[4] = {(unsigned)av1.x, (unsigned)av1.y, (unsigned)av1.z, (unsigned)av1.w};
                mma_f16(acc[0], a0, b0[0], b0[1]);
                mma_f16(acc[1], a0, b0[2], b0[3]);
                mma_f16(acc[2], a0, b1[0], b1[1]);
                mma_f16(acc[3], a0, b1[2], b1[3]);
                mma_f16(acc[4], a1, b0[0], b0[1]);
                mma_f16(acc[5], a1, b0[2], b0[3]);
                mma_f16(acc[6], a1, b1[0], b1[1]);
                mma_f16(acc[7], a1, b1[2], b1[3]);
            }

            // k-split reduction through 2 zs slabs
            if (ksg < 2) {
#pragma unroll
                for (int mt = 0; mt < 2; mt++)
#pragma unroll
                    for (int ci = 0; ci < 4; ci++)
#pragma unroll
                        for (int f = 0; f < 4; f++) {
                            int row = wm * 32 + mt * 16 + gq + (f >> 1) * 8;
                            int col = ci * 8 + 2 * tig + (f & 1);
                            zsw[row * 33 + col] = acc[mt * 4 + ci][f];
                        }
            }
            __syncthreads();
            if (ksg >= 2) {
#pragma unroll
                for (int mt = 0; mt < 2; mt++)
#pragma unroll
                    for (int ci = 0; ci < 4; ci++)
#pragma unroll
                        for (int f = 0; f < 4; f++) {
                            int row = wm * 32 + mt * 16 + gq + (f >> 1) * 8;
                            int col = ci * 8 + 2 * tig + (f & 1);
                            zsw[row * 33 + col] += acc[mt * 4 + ci][f];
                        }
            }
            __syncthreads();

            // gate math: thread owns (batch row gb, units u0..u0+1)
            float hnv[2];
#pragma unroll
            for (int uu = 0; uu < 2; uu++) {
                int u = u0 + uu;
                float zi = zs0[gb * 33 + 0 * 8 + u] + zs1[gb * 33 + 0 * 8 + u] + zxr[uu][0];
                float zj = zs0[gb * 33 + 1 * 8 + u] + zs1[gb * 33 + 1 * 8 + u] + zxr[uu][1];
                float zf = zs0[gb * 33 + 2 * 8 + u] + zs1[gb * 33 + 2 * 8 + u] + zxr[uu][2];
                float zo = zs0[gb * 33 + 3 * 8 + u] + zs1[gb * 33 + 3 * 8 + u] + zxr[uu][3];
                float cn = cst[uu] * sigmoid_fast(zf + 1.0f) + sigmoid_fast(zi) * tanh_fast(zj);
                hnv[uu] = sigmoid_fast(zo) * tanh_fast(cn);
                cst[uu] = cn;
            }
            {
                __half2 hv = __halves2half2(__float2half_rn(hnv[0]), __float2half_rn(hnv[1]));
                ((__half2*)g_hb4[1 - p])[w_idx] = hv;
            }
            if (t == TT - 1) {
                g_hT[gb * HH + (blk << 3) + u0]     = hnv[0];
                g_hT[gb * HH + (blk << 3) + u0 + 1] = hnv[1];
            } else {
#pragma unroll
                for (int uu = 0; uu < 2; uu++) {
                    size_t zb = ((size_t)gb * TT + (t + 1)) * G4 + (blk << 3) + u0 + uu;
#pragma unroll
                    for (int g = 0; g < 4; g++) zxr[uu][g] = __ldcg(&g_zx[zb + (size_t)g * HH]);
                }
            }
            grid_bar(gen);
        }
    }

    // ===== Phase D: out = hT @ w + bo =====
    {
        float* sh = (float*)smem;
        const int b_ = blk;
        for (int k = tid; k < HH; k += NTHR) sh[k] = g_hT[b_ * HH + k];
        __syncthreads();
        for (int c = tid; c < CC; c += NTHR) {
            float acc = bo[c];
#pragma unroll 8
            for (int k = 0; k < HH; k++) acc = fmaf(sh[k], w[k * CC + c], acc);
            out[b_ * CC + c] = acc;
        }
    }
}

extern "C" void kernel_launch(void* const* d_in, const int* in_sizes, int n_in,
                              void* d_out, int out_size) {
    (void)in_sizes; (void)n_in; (void)out_size;
    const float* x  = (const float*)d_in[0];
    const float* Wk = (const float*)d_in[1];
    const float* bk = (const float*)d_in[2];
    const float* w  = (const float*)d_in[3];
    const float* b  = (const float*)d_in[4];
    float* out = (float*)d_out;
    cudaFuncSetAttribute(lstm_persistent, cudaFuncAttributeMaxDynamicSharedMemorySize, DYN_SMEM);
    lstm_persistent<<<NCTA, NTHR, DYN_SMEM>>>(x, Wk, bk, w, b, out);
}

// round 12
// speedup vs baseline: 3.3131x; 1.0437x over previous
#include <cuda_runtime.h>
#include <cuda_fp16.h>

#define BB   128
#define TT   256
#define DD   512
#define HH   1024
#define G4   4096
#define CC   1000
#define NCTA 128
#define NTHR 512

// dynamic smem layout (bytes)
// phase C: W slab [32 rows][2064B] = 66048, then 4 zs slabs of 16896
#define C_Z     66048
#define C_ZSLAB 16896
#define DYN_SMEM 133632
// phase B: Wx slab [64 rows][1040B] = 66560

// ---------------- device scratch ----------------
__device__ float g_zx[(size_t)BB * TT * G4];
// x in MMA-fragment-major layout: tile (rt = row>>4, kt = k>>4) is a 512B block
// at (rt*32+kt)*512; lane L = gq*4+tig holds int4 = its 4 A-registers.
__device__ int4  g_xf[BB * TT * DD / 8];
__device__ int4  g_wx4[DD * G4 / 8];                  // Wx fp16 TRANSPOSED [n:4096][k:512]
__device__ int4  g_wpk4[(size_t)NCTA * 32 * HH / 8];  // Wh fp16 [cta][j:32][k:1024]
// h double buffered, fragment-major (64 k-tiles per row-tile)
__device__ int4  g_hb4[2][BB * HH / 8];
__device__ float g_hT[BB * HH];
__device__ unsigned g_gen;
__device__ unsigned g_cnt;

__device__ __forceinline__ float sigmoid_fast(float x) {
    return __fdividef(1.0f, 1.0f + __expf(-x));
}
__device__ __forceinline__ float tanh_fast(float x) {
    float xc = fminf(fmaxf(x, -15.0f), 15.0f);
    float e = __expf(2.0f * xc);
    return __fdividef(e - 1.0f, e + 1.0f);
}

// fp16 mma
__device__ __forceinline__ void mma_f16(float* c, const unsigned* a, unsigned b0, unsigned b1) {
    asm volatile(
        "mma.sync.aligned.m16n8k16.row.col.f32.f16.f16.f32 "
        "{%0,%1,%2,%3}, {%4,%5,%6,%7}, {%8,%9}, {%0,%1,%2,%3};\n"
        : "+f"(c[0]), "+f"(c[1]), "+f"(c[2]), "+f"(c[3])
        : "r"(a[0]), "r"(a[1]), "r"(a[2]), "r"(a[3]), "r"(b0), "r"(b1));
}
__device__ __forceinline__ void ldsm4(unsigned* r, unsigned a) {
    asm volatile("ldmatrix.sync.aligned.m8n8.x4.shared.b16 {%0,%1,%2,%3}, [%4];\n"
                 : "=r"(r[0]), "=r"(r[1]), "=r"(r[2]), "=r"(r[3]) : "r"(a));
}

// grid barrier: leader-only gpu fences, tight spin
__device__ __forceinline__ void grid_bar(unsigned &gen) {
    __syncthreads();
    if (threadIdx.x == 0) {
        __threadfence();
        if (atomicAdd(&g_cnt, 1u) == NCTA - 1u) {
            g_cnt = 0u;
            __threadfence();
            atomicExch(&g_gen, gen + 1u);
        } else {
            volatile unsigned* vg = &g_gen;
            while (*vg == gen) {}
            __threadfence();
        }
    }
    __syncthreads();
    gen++;
}

__device__ __forceinline__ unsigned packh2(float lo, float hi) {
    __half2 h = __floats2half2_rn(lo, hi);
    return *(unsigned*)&h;
}

extern __shared__ __align__(16) unsigned char smem[];

__global__ void __launch_bounds__(NTHR, 1)
lstm_persistent(const float* __restrict__ x, const float* __restrict__ Wk,
                const float* __restrict__ bk, const float* __restrict__ w,
                const float* __restrict__ bo, float* __restrict__ out) {
    const int tid  = threadIdx.x;
    const int blk  = blockIdx.x;
    const int wid  = tid >> 5;
    const int lane = tid & 31;
    const int gq   = lane >> 2;
    const int tig  = lane & 3;
    const unsigned sb = (unsigned)__cvta_generic_to_shared(smem);

    unsigned gen = atomicAdd(&g_gen, 0u);

    const int gtid = blk * NTHR + tid;
    const int gstr = NCTA * NTHR;

    // ===== Phase A: fp16 conversions + repacks =====
    {
        // x -> fragment-major fp16 (2048 row-tiles x 32 k-tiles x 32 lanes)
        for (int i = gtid; i < 2048 * 32 * 32; i += gstr) {
            int ln = i & 31, kt = (i >> 5) & 31, rt = i >> 10;
            int gq_ = ln >> 2, tg = ln & 3;
            const float* xr0 = x + (size_t)(rt * 16 + gq_) * DD + kt * 16;
            const float* xr1 = xr0 + 8 * DD;
            float2 v0 = *(const float2*)(xr0 + 2 * tg);
            float2 v1 = *(const float2*)(xr1 + 2 * tg);
            float2 v2 = *(const float2*)(xr0 + 8 + 2 * tg);
            float2 v3 = *(const float2*)(xr1 + 8 + 2 * tg);
            int4 o;
            o.x = (int)packh2(v0.x, v0.y);
            o.y = (int)packh2(v1.x, v1.y);
            o.z = (int)packh2(v2.x, v2.y);
            o.w = (int)packh2(v3.x, v3.y);
            g_xf[i] = o;
        }
        unsigned short* wt = (unsigned short*)g_wx4;
        for (int i = gtid; i < G4 * DD; i += gstr) {
            int n = i >> 9, k = i & 511;
            wt[i] = __half_as_ushort(__float2half_rn(Wk[(size_t)k * G4 + n]));
        }
        unsigned short* wpk = (unsigned short*)g_wpk4;
        for (int i = gtid; i < NCTA * 32 * HH; i += gstr) {
            int k  = i & (HH - 1);
            int j  = (i >> 10) & 31;
            int bq = i >> 15;
            int col = ((j >> 3) << 10) + (bq << 3) + (j & 7);
            wpk[i] = __half_as_ushort(__float2half_rn(Wk[(size_t)(DD + k) * G4 + col]));
        }
        int4 z4 = make_int4(0, 0, 0, 0);
        for (int i = gtid; i < BB * HH / 8; i += gstr) {
            g_hb4[0][i] = z4; g_hb4[1][i] = z4;
        }
    }
    grid_bar(gen);

    // ===== Phase B: Zx = x @ Wx + bk  (2 row-tiles per iter share one W ldsm) =====
    {
        const int n0 = (blk & 63) * 64;
        int4* sB4 = (int4*)smem;
        for (int i = tid; i < 64 * 64; i += NTHR) {
            int r = i >> 6, q = i & 63;
            sB4[r * 65 + q] = g_wx4[(n0 + r) * 64 + q];
        }
        __syncthreads();

        const int wm = wid & 3, wn = wid >> 2;
        const unsigned bko = (unsigned)(((lane >> 3) & 1) << 4);
        const int bn = (lane & 7) + ((lane >> 4) << 3);
        const unsigned wb0 = sb + (unsigned)((wn * 16 + bn) * 1040) + bko;

#pragma unroll 1
        for (int s2 = 0; s2 < 128; s2++) {
            const int rt0 = ((blk >> 6) + 4 * s2) * 4 + wm;
            const int rt1 = rt0 + 8;
            const int4* xf0 = g_xf + (size_t)rt0 * 1024 + lane;
            const int4* xf1 = g_xf + (size_t)rt1 * 1024 + lane;
            float acc[2][2][4] = {};
#pragma unroll 4
            for (int kt = 0; kt < 32; kt++) {
                int4 av0 = __ldg(xf0 + kt * 32);
                int4 av1 = __ldg(xf1 + kt * 32);
                unsigned bh[4];
                ldsm4(bh, wb0 + kt * 32);
                unsigned a0[4] = {(unsigned)av0.x, (unsigned)av0.y, (unsigned)av0.z, (unsigned)av0.w};
                unsigned a1[4] = {(unsigned)av1.x, (unsigned)av1.y, (unsigned)av1.z, (unsigned)av1.w};
                mma_f16(acc[0][0], a0, bh[0], bh[1]);
                mma_f16(acc[0][1], a0, bh[2], bh[3]);
                mma_f16(acc[1][0], a1, bh[0], bh[1]);
                mma_f16(acc[1][1], a1, bh[2], bh[3]);
            }
#pragma unroll
            for (int rr = 0; rr < 2; rr++)
#pragma unroll
                for (int nt = 0; nt < 2; nt++)
#pragma unroll
                    for (int f = 0; f < 4; f++) {
                        int row = (rr ? rt1 : rt0) * 16 + gq + (f >> 1) * 8;
                        int cn  = n0 + wn * 16 + nt * 8 + 2 * tig + (f & 1);
                        g_zx[(size_t)row * G4 + cn] = acc[rr][nt][f] + __ldg(&bk[cn]);
                    }
        }
    }
    grid_bar(gen);

    // ===== Phase C: 256 steps. W smem-resident; h fragments LDG'd from L2;
    //        4 zs slabs -> single-sync epilogue =====
    {
        int4* sW4 = (int4*)smem;
        for (int i = tid; i < 32 * 128; i += NTHR) {
            int j = i >> 7, q = i & 127;
            sW4[j * 129 + q] = g_wpk4[((size_t)blk * 32 + j) * 128 + q];
        }
        __syncthreads();

        const int wm  = wid & 3;    // 4 row groups of 32
        const int ksg = wid >> 2;   // 4 k groups of 256
        const unsigned bko = (unsigned)(((lane >> 3) & 1) << 4);
        const int bn = (lane & 7) + ((lane >> 4) << 3);
        const unsigned wB0 = sb + (unsigned)(bn * 2064) + bko + (unsigned)(ksg * 512);
        const unsigned wB1 = wB0 + 16u * 2064u;
        float* zs0 = (float*)(smem + C_Z);
        float* zs1 = (float*)(smem + C_Z + 1 * C_ZSLAB);
        float* zs2 = (float*)(smem + C_Z + 2 * C_ZSLAB);
        float* zs3 = (float*)(smem + C_Z + 3 * C_ZSLAB);
        float* zsw = (float*)(smem + C_Z + ksg * C_ZSLAB);

        const int gb = tid >> 2;          // batch row owned in epilogue
        const int u0 = (tid & 3) << 1;    // first of 2 hidden units (even)
        float cst[2] = {0.f, 0.f};

        // writer address for h (fragment-major): k = blk*8 + u0 (+1 in same word)
        const int kw  = blk * 8 + u0;
        const int w_tile = ((gb >> 4) * 64 + (kw >> 4));
        const int w_word = ((gb & 7) * 4 + (((kw & 7)) >> 1)) * 4 + (((kw & 15) >> 3) * 2 + ((gb >> 3) & 1));
        const int w_idx = w_tile * 128 + w_word;   // index in half2 units

        float zxr[2][4];
#pragma unroll
        for (int uu = 0; uu < 2; uu++) {
            size_t zb = ((size_t)gb * TT + 0) * G4 + (blk << 3) + u0 + uu;
#pragma unroll
            for (int g = 0; g < 4; g++) zxr[uu][g] = __ldcg(&g_zx[zb + (size_t)g * HH]);
        }

        for (int t = 0; t < TT; t++) {
            const int p = t & 1;
            const int4* hp = g_hb4[p];
            float acc[8][4];
#pragma unroll
            for (int i = 0; i < 8; i++)
#pragma unroll
                for (int f = 0; f < 4; f++) acc[i][f] = 0.f;

#pragma unroll 4
            for (int ks = 0; ks < 16; ks++) {
                int kt = ksg * 16 + ks;
                int4 av0 = __ldcg(hp + ((wm * 2 + 0) * 64 + kt) * 32 + lane);
                int4 av1 = __ldcg(hp + ((wm * 2 + 1) * 64 + kt) * 32 + lane);
                unsigned b0[4], b1[4];
                ldsm4(b0, wB0 + ks * 32);
                ldsm4(b1, wB1 + ks * 32);
                unsigned a0[4] = {(unsigned)av0.x, (unsigned)av0.y, (unsigned)av0.z, (unsigned)av0.w};
                unsigned a1[4] = {(unsigned)av1.x, (unsigned)av1.y, (unsigned)av1.z, (unsigned)av1.w};
                mma_f16(acc[0], a0, b0[0], b0[1]);
                mma_f16(acc[1], a0, b0[2], b0[3]);
                mma_f16(acc[2], a0, b1[0], b1[1]);
                mma_f16(acc[3], a0, b1[2], b1[3]);
                mma_f16(acc[4], a1, b0[0], b0[1]);
                mma_f16(acc[5], a1, b0[2], b0[3]);
                mma_f16(acc[6], a1, b1[0], b1[1]);
                mma_f16(acc[7], a1, b1[2], b1[3]);
            }

            // every warp writes its own slab; ONE sync; gate threads sum 4 slabs
#pragma unroll
            for (int mt = 0; mt < 2; mt++)
#pragma unroll
                for (int ci = 0; ci < 4; ci++)
#pragma unroll
                    for (int f = 0; f < 4; f++) {
                        int row = wm * 32 + mt * 16 + gq + (f >> 1) * 8;
                        int col = ci * 8 + 2 * tig + (f & 1);
                        zsw[row * 33 + col] = acc[mt * 4 + ci][f];
                    }
            __syncthreads();

            // gate math: thread owns (batch row gb, units u0..u0+1)
            float hnv[2];
#pragma unroll
            for (int uu = 0; uu < 2; uu++) {
                int u = u0 + uu;
                float zi = zs0[gb * 33 + 0 * 8 + u] + zs1[gb * 33 + 0 * 8 + u]
                         + zs2[gb * 33 + 0 * 8 + u] + zs3[gb * 33 + 0 * 8 + u] + zxr[uu][0];
                float zj = zs0[gb * 33 + 1 * 8 + u] + zs1[gb * 33 + 1 * 8 + u]
                         + zs2[gb * 33 + 1 * 8 + u] + zs3[gb * 33 + 1 * 8 + u] + zxr[uu][1];
                float zf = zs0[gb * 33 + 2 * 8 + u] + zs1[gb * 33 + 2 * 8 + u]
                         + zs2[gb * 33 + 2 * 8 + u] + zs3[gb * 33 + 2 * 8 + u] + zxr[uu][2];
                float zo = zs0[gb * 33 + 3 * 8 + u] + zs1[gb * 33 + 3 * 8 + u]
                         + zs2[gb * 33 + 3 * 8 + u] + zs3[gb * 33 + 3 * 8 + u] + zxr[uu][3];
                float cn = cst[uu] * sigmoid_fast(zf + 1.0f) + sigmoid_fast(zi) * tanh_fast(zj);
                hnv[uu] = sigmoid_fast(zo) * tanh_fast(cn);
                cst[uu] = cn;
            }
            {
                __half2 hv = __halves2half2(__float2half_rn(hnv[0]), __float2half_rn(hnv[1]));
                ((__half2*)g_hb4[1 - p])[w_idx] = hv;
            }
            if (t == TT - 1) {
                g_hT[gb * HH + (blk << 3) + u0]     = hnv[0];
                g_hT[gb * HH + (blk << 3) + u0 + 1] = hnv[1];
            } else {
#pragma unroll
                for (int uu = 0; uu < 2; uu++) {
                    size_t zb = ((size_t)gb * TT + (t + 1)) * G4 + (blk << 3) + u0 + uu;
#pragma unroll
                    for (int g = 0; g < 4; g++) zxr[uu][g] = __ldcg(&g_zx[zb + (size_t)g * HH]);
                }
            }
            grid_bar(gen);
        }
    }

    // ===== Phase D: out = hT @ w + bo =====
    {
        float* sh = (float*)smem;
        const int b_ = blk;
        for (int k = tid; k < HH; k += NTHR) sh[k] = g_hT[b_ * HH + k];
        __syncthreads();
        for (int c = tid; c < CC; c += NTHR) {
            float acc = bo[c];
#pragma unroll 8
            for (int k = 0; k < HH; k++) acc = fmaf(sh[k], w[k * CC + c], acc);
            out[b_ * CC + c] = acc;
        }
    }
}

extern "C" void kernel_launch(void* const* d_in, const int* in_sizes, int n_in,
                              void* d_out, int out_size) {
    (void)in_sizes; (void)n_in; (void)out_size;
    const float* x  = (const float*)d_in[0];
    const float* Wk = (const float*)d_in[1];
    const float* bk = (const float*)d_in[2];
    const float* w  = (const float*)d_in[3];
    const float* b  = (const float*)d_in[4];
    float* out = (float*)d_out;
    cudaFuncSetAttribute(lstm_persistent, cudaFuncAttributeMaxDynamicSharedMemorySize, DYN_SMEM);
    lstm_persistent<<<NCTA, NTHR, DYN_SMEM>>>(x, Wk, bk, w, b, out);
}

// round 13
// speedup vs baseline: 3.3861x; 1.0220x over previous
#include <cuda_runtime.h>
#include <cuda_fp16.h>

#define BB   128
#define TT   256
#define DD   512
#define HH   1024
#define G4   4096
#define CC   1000
#define NCTA 128
#define NTHR 512

// dynamic smem layout (bytes)
// phase C: W slab [32 rows][2064B] = 66048, then 4 zs slabs of 16896
#define C_Z     66048
#define C_ZSLAB 16896
#define DYN_SMEM 133632
// phase B: Wx slab [64 rows][1040B] = 66560

// ---------------- device scratch ----------------
__device__ float g_zx[(size_t)BB * TT * G4];
// x in MMA-fragment-major layout: tile (rt = row>>4, kt = k>>4) is a 512B block
// at (rt*32+kt)*512; lane L = gq*4+tig holds int4 = its 4 A-registers.
__device__ int4  g_xf[BB * TT * DD / 8];
__device__ int4  g_wx4[DD * G4 / 8];                  // Wx fp16 TRANSPOSED [n:4096][k:512]
__device__ int4  g_wpk4[(size_t)NCTA * 32 * HH / 8];  // Wh fp16 [cta][j:32][k:1024]
// h double buffered, fragment-major (64 k-tiles per row-tile)
__device__ int4  g_hb4[2][BB * HH / 8];
__device__ float g_hT[BB * HH];
__device__ unsigned g_gen;
__device__ unsigned g_cnt;

__device__ __forceinline__ float tanh_ap(float x) {
    float y;
    asm("tanh.approx.f32 %0, %1;" : "=f"(y) : "f"(x));
    return y;
}
__device__ __forceinline__ float sigmoid_ap(float x) {
    return fmaf(0.5f, tanh_ap(0.5f * x), 0.5f);
}

// fp16 mma
__device__ __forceinline__ void mma_f16(float* c, const unsigned* a, unsigned b0, unsigned b1) {
    asm volatile(
        "mma.sync.aligned.m16n8k16.row.col.f32.f16.f16.f32 "
        "{%0,%1,%2,%3}, {%4,%5,%6,%7}, {%8,%9}, {%0,%1,%2,%3};\n"
        : "+f"(c[0]), "+f"(c[1]), "+f"(c[2]), "+f"(c[3])
        : "r"(a[0]), "r"(a[1]), "r"(a[2]), "r"(a[3]), "r"(b0), "r"(b1));
}
__device__ __forceinline__ void ldsm4(unsigned* r, unsigned a) {
    asm volatile("ldmatrix.sync.aligned.m8n8.x4.shared.b16 {%0,%1,%2,%3}, [%4];\n"
                 : "=r"(r[0]), "=r"(r[1]), "=r"(r[2]), "=r"(r[3]) : "r"(a));
}

// grid barrier split: arrive (leader announces) / wait (leader polls release)
__device__ __forceinline__ void grid_arrive(unsigned gen) {
    if (threadIdx.x == 0) {
        __threadfence();
        if (atomicAdd(&g_cnt, 1u) == NCTA - 1u) {
            g_cnt = 0u;
            __threadfence();
            atomicExch(&g_gen, gen + 1u);
        }
    }
}
__device__ __forceinline__ void grid_wait(unsigned &gen) {
    if (threadIdx.x == 0) {
        volatile unsigned* vg = &g_gen;
        while (*vg == gen) {}
        __threadfence();
    }
    __syncthreads();
    gen++;
}
__device__ __forceinline__ void grid_bar(unsigned &gen) {
    __syncthreads();
    grid_arrive(gen);
    grid_wait(gen);
}

__device__ __forceinline__ unsigned packh2(float lo, float hi) {
    __half2 h = __floats2half2_rn(lo, hi);
    return *(unsigned*)&h;
}

extern __shared__ __align__(16) unsigned char smem[];

__global__ void __launch_bounds__(NTHR, 1)
lstm_persistent(const float* __restrict__ x, const float* __restrict__ Wk,
                const float* __restrict__ bk, const float* __restrict__ w,
                const float* __restrict__ bo, float* __restrict__ out) {
    const int tid  = threadIdx.x;
    const int blk  = blockIdx.x;
    const int wid  = tid >> 5;
    const int lane = tid & 31;
    const int gq   = lane >> 2;
    const int tig  = lane & 3;
    const unsigned sb = (unsigned)__cvta_generic_to_shared(smem);

    unsigned gen = atomicAdd(&g_gen, 0u);

    const int gtid = blk * NTHR + tid;
    const int gstr = NCTA * NTHR;

    // ===== Phase A: fp16 conversions + repacks =====
    {
        for (int i = gtid; i < 2048 * 32 * 32; i += gstr) {
            int ln = i & 31, kt = (i >> 5) & 31, rt = i >> 10;
            int gq_ = ln >> 2, tg = ln & 3;
            const float* xr0 = x + (size_t)(rt * 16 + gq_) * DD + kt * 16;
            const float* xr1 = xr0 + 8 * DD;
            float2 v0 = *(const float2*)(xr0 + 2 * tg);
            float2 v1 = *(const float2*)(xr1 + 2 * tg);
            float2 v2 = *(const float2*)(xr0 + 8 + 2 * tg);
            float2 v3 = *(const float2*)(xr1 + 8 + 2 * tg);
            int4 o;
            o.x = (int)packh2(v0.x, v0.y);
            o.y = (int)packh2(v1.x, v1.y);
            o.z = (int)packh2(v2.x, v2.y);
            o.w = (int)packh2(v3.x, v3.y);
            g_xf[i] = o;
        }
        unsigned short* wt = (unsigned short*)g_wx4;
        for (int i = gtid; i < G4 * DD; i += gstr) {
            int n = i >> 9, k = i & 511;
            wt[i] = __half_as_ushort(__float2half_rn(Wk[(size_t)k * G4 + n]));
        }
        unsigned short* wpk = (unsigned short*)g_wpk4;
        for (int i = gtid; i < NCTA * 32 * HH; i += gstr) {
            int k  = i & (HH - 1);
            int j  = (i >> 10) & 31;
            int bq = i >> 15;
            int col = ((j >> 3) << 10) + (bq << 3) + (j & 7);
            wpk[i] = __half_as_ushort(__float2half_rn(Wk[(size_t)(DD + k) * G4 + col]));
        }
        int4 z4 = make_int4(0, 0, 0, 0);
        for (int i = gtid; i < BB * HH / 8; i += gstr) {
            g_hb4[0][i] = z4; g_hb4[1][i] = z4;
        }
    }
    grid_bar(gen);

    // ===== Phase B: Zx = x @ Wx + bk  (2 row-tiles per iter share one W ldsm) =====
    {
        const int n0 = (blk & 63) * 64;
        int4* sB4 = (int4*)smem;
        for (int i = tid; i < 64 * 64; i += NTHR) {
            int r = i >> 6, q = i & 63;
            sB4[r * 65 + q] = g_wx4[(n0 + r) * 64 + q];
        }
        __syncthreads();

        const int wm = wid & 3, wn = wid >> 2;
        const unsigned bko = (unsigned)(((lane >> 3) & 1) << 4);
        const int bn = (lane & 7) + ((lane >> 4) << 3);
        const unsigned wb0 = sb + (unsigned)((wn * 16 + bn) * 1040) + bko;

#pragma unroll 1
        for (int s2 = 0; s2 < 128; s2++) {
            const int rt0 = ((blk >> 6) + 4 * s2) * 4 + wm;
            const int rt1 = rt0 + 8;
            const int4* xf0 = g_xf + (size_t)rt0 * 1024 + lane;
            const int4* xf1 = g_xf + (size_t)rt1 * 1024 + lane;
            float acc[2][2][4] = {};
#pragma unroll 4
            for (int kt = 0; kt < 32; kt++) {
                int4 av0 = __ldg(xf0 + kt * 32);
                int4 av1 = __ldg(xf1 + kt * 32);
                unsigned bh[4];
                ldsm4(bh, wb0 + kt * 32);
                unsigned a0[4] = {(unsigned)av0.x, (unsigned)av0.y, (unsigned)av0.z, (unsigned)av0.w};
                unsigned a1[4] = {(unsigned)av1.x, (unsigned)av1.y, (unsigned)av1.z, (unsigned)av1.w};
                mma_f16(acc[0][0], a0, bh[0], bh[1]);
                mma_f16(acc[0][1], a0, bh[2], bh[3]);
                mma_f16(acc[1][0], a1, bh[0], bh[1]);
                mma_f16(acc[1][1], a1, bh[2], bh[3]);
            }
#pragma unroll
            for (int rr = 0; rr < 2; rr++)
#pragma unroll
                for (int nt = 0; nt < 2; nt++)
#pragma unroll
                    for (int f = 0; f < 4; f++) {
                        int row = (rr ? rt1 : rt0) * 16 + gq + (f >> 1) * 8;
                        int cn  = n0 + wn * 16 + nt * 8 + 2 * tig + (f & 1);
                        g_zx[(size_t)row * G4 + cn] = acc[rr][nt][f] + __ldg(&bk[cn]);
                    }
        }
    }
    grid_bar(gen);

    // ===== Phase C: 256 steps. W smem-resident; h fragments LDG'd from L2;
    //        4 zs slabs, single-sync epilogue; split barrier with overlap =====
    {
        int4* sW4 = (int4*)smem;
        for (int i = tid; i < 32 * 128; i += NTHR) {
            int j = i >> 7, q = i & 127;
            sW4[j * 129 + q] = g_wpk4[((size_t)blk * 32 + j) * 128 + q];
        }
        __syncthreads();

        const int wm  = wid & 3;    // 4 row groups of 32
        const int ksg = wid >> 2;   // 4 k groups of 256
        const unsigned bko = (unsigned)(((lane >> 3) & 1) << 4);
        const int bn = (lane & 7) + ((lane >> 4) << 3);
        const unsigned wB0 = sb + (unsigned)(bn * 2064) + bko + (unsigned)(ksg * 512);
        const unsigned wB1 = wB0 + 16u * 2064u;
        float* zs0 = (float*)(smem + C_Z);
        float* zs1 = (float*)(smem + C_Z + 1 * C_ZSLAB);
        float* zs2 = (float*)(smem + C_Z + 2 * C_ZSLAB);
        float* zs3 = (float*)(smem + C_Z + 3 * C_ZSLAB);
        float* zsw = (float*)(smem + C_Z + ksg * C_ZSLAB);

        const int gb = tid >> 2;          // batch row owned in epilogue
        const int u0 = (tid & 3) << 1;    // first of 2 hidden units (even)
        float cst[2] = {0.f, 0.f};

        // writer address for h (fragment-major): k = blk*8 + u0 (+1 in same word)
        const int kw  = blk * 8 + u0;
        const int w_tile = ((gb >> 4) * 64 + (kw >> 4));
        const int w_word = ((gb & 7) * 4 + (((kw & 7)) >> 1)) * 4 + (((kw & 15) >> 3) * 2 + ((gb >> 3) & 1));
        const int w_idx = w_tile * 128 + w_word;   // index in half2 units

        float zxr[2][4];
#pragma unroll
        for (int uu = 0; uu < 2; uu++) {
            size_t zb = ((size_t)gb * TT + 0) * G4 + (blk << 3) + u0 + uu;
#pragma unroll
            for (int g = 0; g < 4; g++) zxr[uu][g] = __ldcg(&g_zx[zb + (size_t)g * HH]);
        }

        for (int t = 0; t < TT; t++) {
            const int p = t & 1;
            const int4* hp0 = g_hb4[p] + ((wm * 2 + 0) * 64 + ksg * 16) * 32 + lane;
            const int4* hp1 = g_hb4[p] + ((wm * 2 + 1) * 64 + ksg * 16) * 32 + lane;
            float acc[8][4];
#pragma unroll
            for (int i = 0; i < 8; i++)
#pragma unroll
                for (int f = 0; f < 4; f++) acc[i][f] = 0.f;

            // 1-ahead LDG pipeline over 16 k-tiles
            int4 av0 = __ldcg(hp0);
            int4 av1 = __ldcg(hp1);
#pragma unroll 4
            for (int ks = 0; ks < 16; ks++) {
                int4 nv0, nv1;
                if (ks < 15) {
                    nv0 = __ldcg(hp0 + (ks + 1) * 32);
                    nv1 = __ldcg(hp1 + (ks + 1) * 32);
                }
                unsigned b0[4], b1[4];
                ldsm4(b0, wB0 + ks * 32);
                ldsm4(b1, wB1 + ks * 32);
                unsigned a0[4] = {(unsigned)av0.x, (unsigned)av0.y, (unsigned)av0.z, (unsigned)av0.w};
                unsigned a1[4] = {(unsigned)av1.x, (unsigned)av1.y, (unsigned)av1.z, (unsigned)av1.w};
                mma_f16(acc[0], a0, b0[0], b0[1]);
                mma_f16(acc[1], a0, b0[2], b0[3]);
                mma_f16(acc[2], a0, b1[0], b1[1]);
                mma_f16(acc[3], a0, b1[2], b1[3]);
                mma_f16(acc[4], a1, b0[0], b0[1]);
                mma_f16(acc[5], a1, b0[2], b0[3]);
                mma_f16(acc[6], a1, b1[0], b1[1]);
                mma_f16(acc[7], a1, b1[2], b1[3]);
                av0 = nv0; av1 = nv1;
            }

            // every warp writes its own slab; ONE sync; gate threads sum 4 slabs
#pragma unroll
            for (int mt = 0; mt < 2; mt++)
#pragma unroll
                for (int ci = 0; ci < 4; ci++)
#pragma unroll
                    for (int f = 0; f < 4; f++) {
                        int row = wm * 32 + mt * 16 + gq + (f >> 1) * 8;
                        int col = ci * 8 + 2 * tig + (f & 1);
                        zsw[row * 33 + col] = acc[mt * 4 + ci][f];
                    }
            __syncthreads();

            // gate math (tanh.approx): thread owns (batch row gb, units u0..u0+1)
            float hnv[2];
#pragma unroll
            for (int uu = 0; uu < 2; uu++) {
                int u = u0 + uu;
                float zi = zs0[gb * 33 + 0 * 8 + u] + zs1[gb * 33 + 0 * 8 + u]
                         + zs2[gb * 33 + 0 * 8 + u] + zs3[gb * 33 + 0 * 8 + u] + zxr[uu][0];
                float zj = zs0[gb * 33 + 1 * 8 + u] + zs1[gb * 33 + 1 * 8 + u]
                         + zs2[gb * 33 + 1 * 8 + u] + zs3[gb * 33 + 1 * 8 + u] + zxr[uu][1];
                float zf = zs0[gb * 33 + 2 * 8 + u] + zs1[gb * 33 + 2 * 8 + u]
                         + zs2[gb * 33 + 2 * 8 + u] + zs3[gb * 33 + 2 * 8 + u] + zxr[uu][2];
                float zo = zs0[gb * 33 + 3 * 8 + u] + zs1[gb * 33 + 3 * 8 + u]
                         + zs2[gb * 33 + 3 * 8 + u] + zs3[gb * 33 + 3 * 8 + u] + zxr[uu][3];
                float cn = cst[uu] * sigmoid_ap(zf + 1.0f) + sigmoid_ap(zi) * tanh_ap(zj);
                hnv[uu] = sigmoid_ap(zo) * tanh_ap(cn);
                cst[uu] = cn;
            }
            {
                __half2 hv = __halves2half2(__float2half_rn(hnv[0]), __float2half_rn(hnv[1]));
                ((__half2*)g_hb4[1 - p])[w_idx] = hv;
            }
            if (t == TT - 1) {
                g_hT[gb * HH + (blk << 3) + u0]     = hnv[0];
                g_hT[gb * HH + (blk << 3) + u0 + 1] = hnv[1];
                grid_bar(gen);
            } else {
                // announce arrival FIRST, then overlap zx prefetch with release propagation
                __syncthreads();
                grid_arrive(gen);
#pragma unroll
                for (int uu = 0; uu < 2; uu++) {
                    size_t zb = ((size_t)gb * TT + (t + 1)) * G4 + (blk << 3) + u0 + uu;
#pragma unroll
                    for (int g = 0; g < 4; g++) zxr[uu][g] = __ldcg(&g_zx[zb + (size_t)g * HH]);
                }
                grid_wait(gen);
            }
        }
    }

    // ===== Phase D: out = hT @ w + bo =====
    {
        float* sh = (float*)smem;
        const int b_ = blk;
        for (int k = tid; k < HH; k += NTHR) sh[k] = g_hT[b_ * HH + k];
        __syncthreads();
        for (int c = tid; c < CC; c += NTHR) {
            float acc = bo[c];
#pragma unroll 8
            for (int k = 0; k < HH; k++) acc = fmaf(sh[k], w[k * CC + c], acc);
            out[b_ * CC + c] = acc;
        }
    }
}

extern "C" void kernel_launch(void* const* d_in, const int* in_sizes, int n_in,
                              void* d_out, int out_size) {
    (void)in_sizes; (void)n_in; (void)out_size;
    const float* x  = (const float*)d_in[0];
    const float* Wk = (const float*)d_in[1];
    const float* bk = (const float*)d_in[2];
    const float* w  = (const float*)d_in[3];
    const float* b  = (const float*)d_in[4];
    float* out = (float*)d_out;
    cudaFuncSetAttribute(lstm_persistent, cudaFuncAttributeMaxDynamicSharedMemorySize, DYN_SMEM);
    lstm_persistent<<<NCTA, NTHR, DYN_SMEM>>>(x, Wk, bk, w, b, out);
}